// round 7
// baseline (speedup 1.0000x reference)
#include <cuda_runtime.h>
#include <cuda_bf16.h>
#include <cstdint>
#include <cstddef>

#define BnW   2048
#define NW    144
#define DIM   256
#define NH    8
#define HD    32
#define NTOK  (BnW * NW)            /* 294912 */
#define QKVN  (3 * DIM)             /* 768 */
#define KSTORE 512                  /* split-bf16 stored K: [hi|lo] */
#define SCALE 0.17677669529663687f

// ---------------- scratch (device globals: allocation-free rule) -------------
__device__ uint32_t      g_qkv[(size_t)NTOK * QKVN];     // packed (hi|lo) bf16 q|k|v
__device__ __nv_bfloat16 g_ax[(size_t)NTOK * KSTORE];    // x ext [Ah|Al]
__device__ __nv_bfloat16 g_attx[(size_t)NTOK * KSTORE];  // attn out ext [Oh|Ol]
__device__ __nv_bfloat16 g_bq[(size_t)QKVN * KSTORE];    // qkv_w ext [Bh|Bl] (q-cols scaled)
__device__ __nv_bfloat16 g_bp[(size_t)DIM * KSTORE];     // proj_w ext
__device__ float         g_sbias[QKVN];                  // scaled qkv bias
__device__ float         g_bias[NH * NW * NW];           // [h][n][m] RPB

// ======================= baseline-PTX tensor-core helpers ====================
__device__ __forceinline__ uint32_t smem_u32(const void* p) {
    uint32_t a;
    asm("{ .reg .u64 t; cvta.to.shared.u64 t, %1; cvt.u32.u64 %0, t; }"
        : "=r"(a) : "l"(p));
    return a;
}
#define LDMX4(r0, r1, r2, r3, addr) \
    asm volatile("ldmatrix.sync.aligned.m8n8.x4.shared.b16 {%0,%1,%2,%3}, [%4];" \
                 : "=r"(r0), "=r"(r1), "=r"(r2), "=r"(r3) : "r"(addr))
#define MMA16816(d, a, b0, b1) \
    asm volatile("mma.sync.aligned.m16n8k16.row.col.f32.bf16.bf16.f32 " \
                 "{%0,%1,%2,%3}, {%4,%5,%6,%7}, {%8,%9}, {%0,%1,%2,%3};" \
                 : "+f"((d)[0]), "+f"((d)[1]), "+f"((d)[2]), "+f"((d)[3]) \
                 : "r"((a)[0]), "r"((a)[1]), "r"((a)[2]), "r"((a)[3]), \
                   "r"(b0), "r"(b1))
#define CPASYNC16(s, g) \
    asm volatile("cp.async.cg.shared.global [%0], [%1], 16;" :: "r"(s), "l"(g))
#define CP_COMMIT() asm volatile("cp.async.commit_group;" ::: "memory")
#define CP_WAIT1()  asm volatile("cp.async.wait_group 1;" ::: "memory")
#define CP_WAIT0()  asm volatile("cp.async.wait_group 0;" ::: "memory")

// ======================= split-bf16 helpers ==================================
__device__ __forceinline__ void bf_split(float f, unsigned short& h, unsigned short& l) {
    __nv_bfloat16 hb = __float2bfloat16(f);
    __nv_bfloat16 lb = __float2bfloat16(f - __bfloat162float(hb));
    h = __bfloat16_as_ushort(hb);
    l = __bfloat16_as_ushort(lb);
}
__device__ __forceinline__ uint32_t pack_hl(float f) {
    unsigned short h, l;
    bf_split(f, h, l);
    return (uint32_t)h | ((uint32_t)l << 16);
}
__device__ __forceinline__ void split2(float x, float y, uint32_t& hp, uint32_t& lp) {
    unsigned short hx, lx, hy, ly;
    bf_split(x, hx, lx);
    bf_split(y, hy, ly);
    hp = (uint32_t)hx | ((uint32_t)hy << 16);
    lp = (uint32_t)lx | ((uint32_t)ly << 16);
}

// x [NTOK,256] fp32 -> g_ax [NTOK,512] = [Ah|Al]
__global__ __launch_bounds__(256) void conv_x_kernel(const float* __restrict__ x) {
    size_t i = (size_t)blockIdx.x * 256 + threadIdx.x;   // over NTOK*64
    size_t row = i >> 6;
    int c4 = (int)(i & 63) * 4;
    float4 v = *reinterpret_cast<const float4*>(x + row * DIM + c4);
    ushort4 hv, lv;
    bf_split(v.x, hv.x, lv.x); bf_split(v.y, hv.y, lv.y);
    bf_split(v.z, hv.z, lv.z); bf_split(v.w, hv.w, lv.w);
    __nv_bfloat16* base = g_ax + row * KSTORE;
    *reinterpret_cast<ushort4*>(base + c4)       = hv;
    *reinterpret_cast<ushort4*>(base + 256 + c4) = lv;
}

// both weight conversions in ONE launch.
// blocks [0, 768): qkv_w (N=768, scale q cols); blocks [768, 1024): proj_w (N=256)
__global__ __launch_bounds__(256) void conv_w_all_kernel(
    const float* __restrict__ qkv_w, const float* __restrict__ proj_w) {
    int blk = blockIdx.x;
    const float* w;
    __nv_bfloat16* Bext;
    int N, nscale, i;
    if (blk < 768) {
        w = qkv_w; Bext = g_bq; N = QKVN; nscale = DIM;
        i = blk * 256 + threadIdx.x;
    } else {
        w = proj_w; Bext = g_bp; N = DIM; nscale = 0;
        i = (blk - 768) * 256 + threadIdx.x;
    }
    int n = i >> 8, k = i & 255;
    float val = w[k * N + n];
    if (n < nscale) val *= SCALE;
    unsigned short h, l;
    bf_split(val, h, l);
    Bext[(size_t)n * KSTORE + k]       = __ushort_as_bfloat16(h);
    Bext[(size_t)n * KSTORE + 256 + k] = __ushort_as_bfloat16(l);
}

// merged: rpb gather (blocks 0..80) + scaled qkv bias (blocks 81..83)
__global__ __launch_bounds__(256) void bias_all_kernel(
    const float* __restrict__ rpb, const int* __restrict__ rel,
    const float* __restrict__ qkv_b) {
    int blk = blockIdx.x;
    if (blk < 81) {
        int idx = blk * 256 + threadIdx.x;
        if (idx < NW * NW) {
            int r = rel[idx];
#pragma unroll
            for (int h = 0; h < NH; h++)
                g_bias[h * (NW * NW) + idx] = rpb[r * NH + h];
        }
    } else {
        int i = (blk - 81) * 256 + threadIdx.x;
        if (i < QKVN) g_sbias[i] = qkv_b[i] * (i < DIM ? SCALE : 1.0f);
    }
}

// ======================= mma.sync GEMM: C = Aext @ Bext^T + bias =============
// grouped K: for g=0..7 load (Ah_g, Al_g, Bh_g, Bl_g) once; MMA terms
// Ah*Bh + Al*Bh + Ah*Bl with Ah fragments reused from registers.
#define SPITCH 80
#define STAGE_BYTES (128 * SPITCH)          /* 10240 per buffer */
#define SMEM_GEMM (8 * STAGE_BYTES)         /* 81920: 4 bufs x 2 stages */

template <bool PACK>
__global__ __launch_bounds__(256, 2) void gemm_mma_kernel(
    const __nv_bfloat16* __restrict__ Aext,
    const __nv_bfloat16* __restrict__ Bext,
    const float* __restrict__ bias,
    void* __restrict__ Cout, int Ntot) {
    extern __shared__ char gsm[];
    const uint32_t sAb = smem_u32(gsm);                 // Ah|Al per stage
    const uint32_t sBb = sAb + 4 * STAGE_BYTES;         // Bh|Bl per stage

    const int tid = threadIdx.x;
    const int w = tid >> 5, l = tid & 31;
    const int wm = w & 1, wn = w >> 1;
    const int tileN = blockIdx.x, tileM = blockIdx.y;

    const char* Ab = reinterpret_cast<const char*>(Aext) +
                     (size_t)tileM * 128 * (KSTORE * 2);
    const char* Bb = reinterpret_cast<const char*>(Bext) +
                     (size_t)tileN * 128 * (KSTORE * 2);

    const int lrow = tid >> 2;              // 0..63
    const int lseg = (tid & 3) * 16;        // 0..48

    float acc[4][4][4];
#pragma unroll
    for (int mf = 0; mf < 4; mf++)
#pragma unroll
        for (int nf = 0; nf < 4; nf++)
#pragma unroll
            for (int r = 0; r < 4; r++) acc[mf][nf][r] = 0.f;

    // stage s holds: sAb + s*2*STAGE (Ah), +STAGE (Al); same for B.
#define ISSUE_GROUP(gg) do {                                                      \
        const int _g = (gg);                                                      \
        const uint32_t _sa = sAb + (uint32_t)(_g & 1) * (2 * STAGE_BYTES);        \
        const uint32_t _sb = sBb + (uint32_t)(_g & 1) * (2 * STAGE_BYTES);        \
        const size_t _r1 = (size_t)lrow * (KSTORE * 2);                           \
        const size_t _r2 = (size_t)(lrow + 64) * (KSTORE * 2);                    \
        const int _hc = _g * 64 + lseg;                                           \
        const int _lc = 512 + _g * 64 + lseg;                                     \
        CPASYNC16(_sa + lrow * SPITCH + lseg,              Ab + _r1 + _hc);       \
        CPASYNC16(_sa + (lrow + 64) * SPITCH + lseg,       Ab + _r2 + _hc);       \
        CPASYNC16(_sa + STAGE_BYTES + lrow * SPITCH + lseg,        Ab + _r1 + _lc); \
        CPASYNC16(_sa + STAGE_BYTES + (lrow + 64) * SPITCH + lseg, Ab + _r2 + _lc); \
        CPASYNC16(_sb + lrow * SPITCH + lseg,              Bb + _r1 + _hc);       \
        CPASYNC16(_sb + (lrow + 64) * SPITCH + lseg,       Bb + _r2 + _hc);       \
        CPASYNC16(_sb + STAGE_BYTES + lrow * SPITCH + lseg,        Bb + _r1 + _lc); \
        CPASYNC16(_sb + STAGE_BYTES + (lrow + 64) * SPITCH + lseg, Bb + _r2 + _lc); \
        CP_COMMIT();                                                              \
    } while (0)

    ISSUE_GROUP(0);
    ISSUE_GROUP(1);

    const uint32_t aRowOff = (uint32_t)(wm * 64 + (l & 15)) * SPITCH + (l >> 4) * 16;
    const uint32_t bRowOff = (uint32_t)(wn * 32 + ((l >> 4) * 8 + (l & 7))) * SPITCH +
                             ((l >> 3) & 1) * 16;

    for (int g = 0; g < 8; g++) {
        if (g < 7) CP_WAIT1(); else CP_WAIT0();
        __syncthreads();

        const uint32_t st = (uint32_t)(g & 1) * (2 * STAGE_BYTES);
        const uint32_t aH = sAb + st + aRowOff;
        const uint32_t aL = aH + STAGE_BYTES;
        const uint32_t bH = sBb + st + bRowOff;
        const uint32_t bL = bH + STAGE_BYTES;

#pragma unroll
        for (int ks = 0; ks < 2; ks++) {
            uint32_t ah[4][4], al[4][4], bf[2][4];
            // Ah + Bh -> term1
#pragma unroll
            for (int mf = 0; mf < 4; mf++)
                LDMX4(ah[mf][0], ah[mf][1], ah[mf][2], ah[mf][3],
                      aH + mf * (16 * SPITCH) + ks * 32);
#pragma unroll
            for (int n2 = 0; n2 < 2; n2++)
                LDMX4(bf[n2][0], bf[n2][1], bf[n2][2], bf[n2][3],
                      bH + n2 * (16 * SPITCH) + ks * 32);
#pragma unroll
            for (int mf = 0; mf < 4; mf++)
#pragma unroll
                for (int nf = 0; nf < 4; nf++)
                    MMA16816(acc[mf][nf], ah[mf],
                             bf[nf >> 1][(nf & 1) * 2],
                             bf[nf >> 1][(nf & 1) * 2 + 1]);
            // Al + Bh -> term2
#pragma unroll
            for (int mf = 0; mf < 4; mf++)
                LDMX4(al[mf][0], al[mf][1], al[mf][2], al[mf][3],
                      aL + mf * (16 * SPITCH) + ks * 32);
#pragma unroll
            for (int mf = 0; mf < 4; mf++)
#pragma unroll
                for (int nf = 0; nf < 4; nf++)
                    MMA16816(acc[mf][nf], al[mf],
                             bf[nf >> 1][(nf & 1) * 2],
                             bf[nf >> 1][(nf & 1) * 2 + 1]);
            // Ah + Bl -> term3 (reuse ah regs, overwrite bf)
#pragma unroll
            for (int n2 = 0; n2 < 2; n2++)
                LDMX4(bf[n2][0], bf[n2][1], bf[n2][2], bf[n2][3],
                      bL + n2 * (16 * SPITCH) + ks * 32);
#pragma unroll
            for (int mf = 0; mf < 4; mf++)
#pragma unroll
                for (int nf = 0; nf < 4; nf++)
                    MMA16816(acc[mf][nf], ah[mf],
                             bf[nf >> 1][(nf & 1) * 2],
                             bf[nf >> 1][(nf & 1) * 2 + 1]);
        }
        __syncthreads();
        if (g + 2 < 8) ISSUE_GROUP(g + 2);
    }
#undef ISSUE_GROUP

    const int rbase = tileM * 128 + wm * 64 + (l >> 2);
    const int cbase = tileN * 128 + wn * 32 + (l & 3) * 2;
#pragma unroll
    for (int mf = 0; mf < 4; mf++) {
#pragma unroll
        for (int nf = 0; nf < 4; nf++) {
            const int col = cbase + nf * 8;
            const float b0 = bias[col], b1 = bias[col + 1];
            const size_t r0 = (size_t)(rbase + mf * 16) * Ntot + col;
            const size_t r1 = r0 + (size_t)8 * Ntot;
            if (PACK) {
                uint32_t* C = reinterpret_cast<uint32_t*>(Cout);
                *reinterpret_cast<uint2*>(C + r0) =
                    make_uint2(pack_hl(acc[mf][nf][0] + b0), pack_hl(acc[mf][nf][1] + b1));
                *reinterpret_cast<uint2*>(C + r1) =
                    make_uint2(pack_hl(acc[mf][nf][2] + b0), pack_hl(acc[mf][nf][3] + b1));
            } else {
                float* C = reinterpret_cast<float*>(Cout);
                *reinterpret_cast<float2*>(C + r0) =
                    make_float2(acc[mf][nf][0] + b0, acc[mf][nf][1] + b1);
                *reinterpret_cast<float2*>(C + r1) =
                    make_float2(acc[mf][nf][2] + b0, acc[mf][nf][3] + b1);
            }
        }
    }
}

// ======================= tensor-core attention v2 ============================
// one block per (head, window): 288 threads = 9 warps, warp grid 3M x 3N.
#define QPITCH 144
#define KPITCH 144
#define VPITCH 592
#define OPITCH 36
#define OFF_Q   0
#define OFF_K   (144 * QPITCH)
#define OFF_V   (OFF_K + 144 * KPITCH)
#define OFF_O   (OFF_V + 32 * VPITCH)
#define OFF_MX  (OFF_O + 144 * OPITCH * 4)
#define OFF_SM2 (OFF_MX + 144 * 3 * 4)
#define SMEM_ATTN (OFF_SM2 + 144 * 3 * 4)

__global__ __launch_bounds__(288, 1) void attn_tc_kernel() {
    extern __shared__ char sm[];
    const uint32_t sb = smem_u32(sm);
    const int tid = threadIdx.x, l = tid & 31, w = tid >> 5;
    const int wm = w / 3, wn = w % 3;
    const int h = blockIdx.x, b = blockIdx.y;
    const size_t tokBase = (size_t)b * NW;
    float* O = reinterpret_cast<float*>(sm + OFF_O);

    for (int idx = tid; idx < 144 * OPITCH / 2; idx += 288)
        *reinterpret_cast<float2*>(O + idx * 2) = make_float2(0.f, 0.f);

    for (int idx = tid; idx < 144 * 8; idx += 288) {
        int r = idx >> 3, d4 = (idx & 7) * 4;
        uint4 q = *reinterpret_cast<const uint4*>(
            g_qkv + (tokBase + r) * QKVN + h * HD + d4);
        char* qb = sm + OFF_Q + r * QPITCH + d4 * 2;
        *reinterpret_cast<uint32_t*>(qb)      = __byte_perm(q.x, q.y, 0x5410);
        *reinterpret_cast<uint32_t*>(qb + 4)  = __byte_perm(q.z, q.w, 0x5410);
        *reinterpret_cast<uint32_t*>(qb + 64) = __byte_perm(q.x, q.y, 0x7632);
        *reinterpret_cast<uint32_t*>(qb + 68) = __byte_perm(q.z, q.w, 0x7632);
        uint4 k = *reinterpret_cast<const uint4*>(
            g_qkv + (tokBase + r) * QKVN + DIM + h * HD + d4);
        char* kb = sm + OFF_K + r * KPITCH + d4 * 2;
        *reinterpret_cast<uint32_t*>(kb)      = __byte_perm(k.x, k.y, 0x5410);
        *reinterpret_cast<uint32_t*>(kb + 4)  = __byte_perm(k.z, k.w, 0x5410);
        *reinterpret_cast<uint32_t*>(kb + 64) = __byte_perm(k.x, k.y, 0x7632);
        *reinterpret_cast<uint32_t*>(kb + 68) = __byte_perm(k.z, k.w, 0x7632);
    }
    for (int idx = tid; idx < 144 * 8; idx += 288) {
        int m = idx >> 3, d4 = (idx & 7) * 4;
        uint4 e = *reinterpret_cast<const uint4*>(
            g_qkv + (tokBase + m) * QKVN + 2 * DIM + h * HD + d4);
        uint32_t ev[4] = {e.x, e.y, e.z, e.w};
#pragma unroll
        for (int j = 0; j < 4; j++) {
            char* base = sm + OFF_V + (d4 + j) * VPITCH + 2 * m;
            *reinterpret_cast<unsigned short*>(base)       = (unsigned short)ev[j];
            *reinterpret_cast<unsigned short*>(base + 288) = (unsigned short)(ev[j] >> 16);
        }
    }
    __syncthreads();

    float accS[3][6][4];
#pragma unroll
    for (int mt = 0; mt < 3; mt++)
#pragma unroll
        for (int j = 0; j < 6; j++)
#pragma unroll
            for (int e = 0; e < 4; e++) accS[mt][j][e] = 0.f;

    const uint32_t aBase = sb + OFF_Q + (wm * 48 + (l & 15)) * QPITCH + (l >> 4) * 16;
    const uint32_t bBase = sb + OFF_K +
        (wn * 48 + ((l >> 4) & 1) * 8 + (l & 7)) * KPITCH + ((l >> 3) & 1) * 16;
#pragma unroll
    for (int pass = 0; pass < 3; pass++) {
        const int aoff = (pass == 1) ? 64 : 0;
        const int boff = (pass == 2) ? 64 : 0;
#pragma unroll
        for (int ks = 0; ks < 2; ks++) {
            uint32_t afr[3][4], bfr[3][4];
#pragma unroll
            for (int mt = 0; mt < 3; mt++)
                LDMX4(afr[mt][0], afr[mt][1], afr[mt][2], afr[mt][3],
                      aBase + mt * (16 * QPITCH) + aoff + ks * 32);
#pragma unroll
            for (int jp = 0; jp < 3; jp++)
                LDMX4(bfr[jp][0], bfr[jp][1], bfr[jp][2], bfr[jp][3],
                      bBase + jp * (16 * KPITCH) + boff + ks * 32);
#pragma unroll
            for (int mt = 0; mt < 3; mt++)
#pragma unroll
                for (int j = 0; j < 6; j++)
                    MMA16816(accS[mt][j], afr[mt],
                             bfr[j >> 1][(j & 1) * 2],
                             bfr[j >> 1][(j & 1) * 2 + 1]);
        }
    }

    const float* bh = g_bias + h * (NW * NW);
    float rmax[3][2];
#pragma unroll
    for (int mt = 0; mt < 3; mt++) { rmax[mt][0] = -1e30f; rmax[mt][1] = -1e30f; }
#pragma unroll
    for (int mt = 0; mt < 3; mt++) {
        const int r = wm * 48 + mt * 16 + (l >> 2);
#pragma unroll
        for (int j = 0; j < 6; j++) {
            const int c = wn * 48 + j * 8 + (l & 3) * 2;
            float2 b0 = *reinterpret_cast<const float2*>(bh + r * NW + c);
            float2 b1 = *reinterpret_cast<const float2*>(bh + (r + 8) * NW + c);
            accS[mt][j][0] += b0.x; accS[mt][j][1] += b0.y;
            accS[mt][j][2] += b1.x; accS[mt][j][3] += b1.y;
            rmax[mt][0] = fmaxf(rmax[mt][0], fmaxf(accS[mt][j][0], accS[mt][j][1]));
            rmax[mt][1] = fmaxf(rmax[mt][1], fmaxf(accS[mt][j][2], accS[mt][j][3]));
        }
    }
#pragma unroll
    for (int mt = 0; mt < 3; mt++) {
#pragma unroll
        for (int o = 1; o <= 2; o <<= 1) {
            rmax[mt][0] = fmaxf(rmax[mt][0], __shfl_xor_sync(0xffffffff, rmax[mt][0], o));
            rmax[mt][1] = fmaxf(rmax[mt][1], __shfl_xor_sync(0xffffffff, rmax[mt][1], o));
        }
    }
    float* mx = reinterpret_cast<float*>(sm + OFF_MX);
    if ((l & 3) == 0) {
#pragma unroll
        for (int mt = 0; mt < 3; mt++) {
            mx[(wm * 48 + mt * 16 + (l >> 2)) * 3 + wn]     = rmax[mt][0];
            mx[(wm * 48 + mt * 16 + 8 + (l >> 2)) * 3 + wn] = rmax[mt][1];
        }
    }
    __syncthreads();

    float gmax[3][2], rsum[3][2];
#pragma unroll
    for (int mt = 0; mt < 3; mt++) {
        const int r0 = (wm * 48 + mt * 16 + (l >> 2)) * 3;
        const int r1 = (wm * 48 + mt * 16 + 8 + (l >> 2)) * 3;
        gmax[mt][0] = fmaxf(fmaxf(mx[r0], mx[r0 + 1]), mx[r0 + 2]);
        gmax[mt][1] = fmaxf(fmaxf(mx[r1], mx[r1 + 1]), mx[r1 + 2]);
        rsum[mt][0] = 0.f; rsum[mt][1] = 0.f;
    }
#pragma unroll
    for (int mt = 0; mt < 3; mt++)
#pragma unroll
        for (int j = 0; j < 6; j++) {
            accS[mt][j][0] = __expf(accS[mt][j][0] - gmax[mt][0]);
            accS[mt][j][1] = __expf(accS[mt][j][1] - gmax[mt][0]);
            accS[mt][j][2] = __expf(accS[mt][j][2] - gmax[mt][1]);
            accS[mt][j][3] = __expf(accS[mt][j][3] - gmax[mt][1]);
            rsum[mt][0] += accS[mt][j][0] + accS[mt][j][1];
            rsum[mt][1] += accS[mt][j][2] + accS[mt][j][3];
        }
#pragma unroll
    for (int mt = 0; mt < 3; mt++) {
#pragma unroll
        for (int o = 1; o <= 2; o <<= 1) {
            rsum[mt][0] += __shfl_xor_sync(0xffffffff, rsum[mt][0], o);
            rsum[mt][1] += __shfl_xor_sync(0xffffffff, rsum[mt][1], o);
        }
    }
    float* sm2 = reinterpret_cast<float*>(sm + OFF_SM2);
    if ((l & 3) == 0) {
#pragma unroll
        for (int mt = 0; mt < 3; mt++) {
            sm2[(wm * 48 + mt * 16 + (l >> 2)) * 3 + wn]     = rsum[mt][0];
            sm2[(wm * 48 + mt * 16 + 8 + (l >> 2)) * 3 + wn] = rsum[mt][1];
        }
    }
    __syncthreads();

    float inv[3][2];
#pragma unroll
    for (int mt = 0; mt < 3; mt++) {
        const int r0 = (wm * 48 + mt * 16 + (l >> 2)) * 3;
        const int r1 = (wm * 48 + mt * 16 + 8 + (l >> 2)) * 3;
        inv[mt][0] = 1.0f / (sm2[r0] + sm2[r0 + 1] + sm2[r0 + 2]);
        inv[mt][1] = 1.0f / (sm2[r1] + sm2[r1 + 1] + sm2[r1 + 2]);
    }
    uint32_t ph[3][3][4], pl[3][3][4];
#pragma unroll
    for (int mt = 0; mt < 3; mt++)
#pragma unroll
        for (int kk = 0; kk < 3; kk++) {
            const int j0 = 2 * kk, j1 = 2 * kk + 1;
            split2(accS[mt][j0][0] * inv[mt][0], accS[mt][j0][1] * inv[mt][0],
                   ph[mt][kk][0], pl[mt][kk][0]);
            split2(accS[mt][j0][2] * inv[mt][1], accS[mt][j0][3] * inv[mt][1],
                   ph[mt][kk][1], pl[mt][kk][1]);
            split2(accS[mt][j1][0] * inv[mt][0], accS[mt][j1][1] * inv[mt][0],
                   ph[mt][kk][2], pl[mt][kk][2]);
            split2(accS[mt][j1][2] * inv[mt][1], accS[mt][j1][3] * inv[mt][1],
                   ph[mt][kk][3], pl[mt][kk][3]);
        }

    float accO[3][4][4];
#pragma unroll
    for (int mt = 0; mt < 3; mt++)
#pragma unroll
        for (int j = 0; j < 4; j++)
#pragma unroll
            for (int e = 0; e < 4; e++) accO[mt][j][e] = 0.f;

    const uint32_t vBase = sb + OFF_V +
        (((l >> 4) & 1) * 8 + (l & 7)) * VPITCH + ((l >> 3) & 1) * 16 +
        2 * (wn * 48);
#pragma unroll
    for (int kk = 0; kk < 3; kk++) {
        uint32_t vh[2][4], vl[2][4];
#pragma unroll
        for (int jp = 0; jp < 2; jp++)
            LDMX4(vh[jp][0], vh[jp][1], vh[jp][2], vh[jp][3],
                  vBase + jp * (16 * VPITCH) + kk * 32);
#pragma unroll
        for (int mt = 0; mt < 3; mt++)
#pragma unroll
            for (int j = 0; j < 4; j++) {
                MMA16816(accO[mt][j], ph[mt][kk],
                         vh[j >> 1][(j & 1) * 2], vh[j >> 1][(j & 1) * 2 + 1]);
                MMA16816(accO[mt][j], pl[mt][kk],
                         vh[j >> 1][(j & 1) * 2], vh[j >> 1][(j & 1) * 2 + 1]);
            }
#pragma unroll
        for (int jp = 0; jp < 2; jp++)
            LDMX4(vl[jp][0], vl[jp][1], vl[jp][2], vl[jp][3],
                  vBase + jp * (16 * VPITCH) + kk * 32 + 288);
#pragma unroll
        for (int mt = 0; mt < 3; mt++)
#pragma unroll
            for (int j = 0; j < 4; j++)
                MMA16816(accO[mt][j], ph[mt][kk],
                         vl[j >> 1][(j & 1) * 2], vl[j >> 1][(j & 1) * 2 + 1]);
    }

#pragma unroll
    for (int mt = 0; mt < 3; mt++) {
        const int r = wm * 48 + mt * 16 + (l >> 2);
#pragma unroll
        for (int j = 0; j < 4; j++) {
            const int cc = j * 8 + (l & 3) * 2;
            atomicAdd(&O[r * OPITCH + cc],           accO[mt][j][0]);
            atomicAdd(&O[r * OPITCH + cc + 1],       accO[mt][j][1]);
            atomicAdd(&O[(r + 8) * OPITCH + cc],     accO[mt][j][2]);
            atomicAdd(&O[(r + 8) * OPITCH + cc + 1], accO[mt][j][3]);
        }
    }
    __syncthreads();

    for (int idx = tid; idx < 144 * 16; idx += 288) {
        const int r = idx >> 4, d = (idx & 15) * 2;
        uint32_t hp, lp;
        split2(O[r * OPITCH + d], O[r * OPITCH + d + 1], hp, lp);
        __nv_bfloat16* o = g_attx + (tokBase + r) * KSTORE + h * HD + d;
        *reinterpret_cast<uint32_t*>(o)       = hp;
        *reinterpret_cast<uint32_t*>(o + 256) = lp;
    }
}

// ---------------- launch ------------------------------------------------------
extern "C" void kernel_launch(void* const* d_in, const int* in_sizes, int n_in,
                              void* d_out, int out_size) {
    const float* x      = (const float*)d_in[0];
    const float* qkv_w  = (const float*)d_in[1];
    const float* qkv_b  = (const float*)d_in[2];
    const float* proj_w = (const float*)d_in[3];
    const float* proj_b = (const float*)d_in[4];
    const float* rpb    = (const float*)d_in[5];
    const int*   rel    = (const int*)d_in[6];

    uint32_t* qkvbuf = nullptr;
    __nv_bfloat16 *axp = nullptr, *attxp = nullptr, *bqp = nullptr, *bpp = nullptr;
    float* sbp = nullptr;
    cudaGetSymbolAddress((void**)&qkvbuf, g_qkv);
    cudaGetSymbolAddress((void**)&axp,   g_ax);
    cudaGetSymbolAddress((void**)&attxp, g_attx);
    cudaGetSymbolAddress((void**)&bqp,   g_bq);
    cudaGetSymbolAddress((void**)&bpp,   g_bp);
    cudaGetSymbolAddress((void**)&sbp,   g_sbias);

    static bool attr_done = false;
    if (!attr_done) {
        cudaFuncSetAttribute(attn_tc_kernel,
                             cudaFuncAttributeMaxDynamicSharedMemorySize, SMEM_ATTN);
        cudaFuncSetAttribute(gemm_mma_kernel<true>,
                             cudaFuncAttributeMaxDynamicSharedMemorySize, SMEM_GEMM);
        cudaFuncSetAttribute(gemm_mma_kernel<false>,
                             cudaFuncAttributeMaxDynamicSharedMemorySize, SMEM_GEMM);
        attr_done = true;
    }

    // launch order chosen so index 3 (the profiled one) = QKV GEMM
    conv_x_kernel<<<(NTOK * 64) / 256, 256>>>(x);                    // 0
    conv_w_all_kernel<<<1024, 256>>>(qkv_w, proj_w);                 // 1
    bias_all_kernel<<<84, 256>>>(rpb, rel, qkv_b);                   // 2
    gemm_mma_kernel<true><<<dim3(QKVN / 128, NTOK / 128), 256, SMEM_GEMM>>>(
        axp, bqp, sbp, qkvbuf, QKVN);                                // 3 <- profiled
    attn_tc_kernel<<<dim3(NH, BnW), 288, SMEM_ATTN>>>();             // 4
    gemm_mma_kernel<false><<<dim3(DIM / 128, NTOK / 128), 256, SMEM_GEMM>>>(
        attxp, bpp, proj_b, d_out, DIM);                             // 5
}

// round 8
// speedup vs baseline: 1.1362x; 1.1362x over previous
#include <cuda_runtime.h>
#include <cuda_bf16.h>
#include <cstdint>
#include <cstddef>

#define BnW   2048
#define NW    144
#define DIM   256
#define NH    8
#define HD    32
#define NTOK  (BnW * NW)            /* 294912 */
#define QKVN  (3 * DIM)             /* 768 */
#define KSTORE 512                  /* split-bf16 stored K: [hi|lo] */
#define SCALE 0.17677669529663687f

// ---------------- scratch (device globals: allocation-free rule) -------------
__device__ uint32_t      g_qkv[(size_t)NTOK * QKVN];     // packed (hi|lo) bf16 q|k|v
__device__ __nv_bfloat16 g_ax[(size_t)NTOK * KSTORE];    // x ext [Ah|Al]
__device__ __nv_bfloat16 g_attx[(size_t)NTOK * KSTORE];  // attn out ext [Oh|Ol]
__device__ __nv_bfloat16 g_bq[(size_t)QKVN * KSTORE];    // qkv_w ext [Bh|Bl] (q-cols scaled)
__device__ __nv_bfloat16 g_bp[(size_t)DIM * KSTORE];     // proj_w ext
__device__ float         g_sbias[QKVN];                  // scaled qkv bias
__device__ float         g_bias[NH * NW * NW];           // [h][n][m] RPB

// ======================= baseline-PTX tensor-core helpers ====================
__device__ __forceinline__ uint32_t smem_u32(const void* p) {
    uint32_t a;
    asm("{ .reg .u64 t; cvta.to.shared.u64 t, %1; cvt.u32.u64 %0, t; }"
        : "=r"(a) : "l"(p));
    return a;
}
#define LDMX4(r0, r1, r2, r3, addr) \
    asm volatile("ldmatrix.sync.aligned.m8n8.x4.shared.b16 {%0,%1,%2,%3}, [%4];" \
                 : "=r"(r0), "=r"(r1), "=r"(r2), "=r"(r3) : "r"(addr))
#define MMA16816(d, a, b0, b1) \
    asm volatile("mma.sync.aligned.m16n8k16.row.col.f32.bf16.bf16.f32 " \
                 "{%0,%1,%2,%3}, {%4,%5,%6,%7}, {%8,%9}, {%0,%1,%2,%3};" \
                 : "+f"((d)[0]), "+f"((d)[1]), "+f"((d)[2]), "+f"((d)[3]) \
                 : "r"((a)[0]), "r"((a)[1]), "r"((a)[2]), "r"((a)[3]), \
                   "r"(b0), "r"(b1))
#define CPASYNC16(s, g) \
    asm volatile("cp.async.cg.shared.global [%0], [%1], 16;" :: "r"(s), "l"(g))
#define CP_COMMIT() asm volatile("cp.async.commit_group;" ::: "memory")
#define CP_WAIT1()  asm volatile("cp.async.wait_group 1;" ::: "memory")
#define CP_WAIT0()  asm volatile("cp.async.wait_group 0;" ::: "memory")

// ======================= split-bf16 helpers ==================================
__device__ __forceinline__ void bf_split(float f, unsigned short& h, unsigned short& l) {
    __nv_bfloat16 hb = __float2bfloat16(f);
    __nv_bfloat16 lb = __float2bfloat16(f - __bfloat162float(hb));
    h = __bfloat16_as_ushort(hb);
    l = __bfloat16_as_ushort(lb);
}
__device__ __forceinline__ uint32_t pack_hl(float f) {
    unsigned short h, l;
    bf_split(f, h, l);
    return (uint32_t)h | ((uint32_t)l << 16);
}
__device__ __forceinline__ void split2(float x, float y, uint32_t& hp, uint32_t& lp) {
    unsigned short hx, lx, hy, ly;
    bf_split(x, hx, lx);
    bf_split(y, hy, ly);
    hp = (uint32_t)hx | ((uint32_t)hy << 16);
    lp = (uint32_t)lx | ((uint32_t)ly << 16);
}

// x [NTOK,256] fp32 -> g_ax [NTOK,512] = [Ah|Al]
__global__ __launch_bounds__(256) void conv_x_kernel(const float* __restrict__ x) {
    size_t i = (size_t)blockIdx.x * 256 + threadIdx.x;   // over NTOK*64
    size_t row = i >> 6;
    int c4 = (int)(i & 63) * 4;
    float4 v = *reinterpret_cast<const float4*>(x + row * DIM + c4);
    ushort4 hv, lv;
    bf_split(v.x, hv.x, lv.x); bf_split(v.y, hv.y, lv.y);
    bf_split(v.z, hv.z, lv.z); bf_split(v.w, hv.w, lv.w);
    __nv_bfloat16* base = g_ax + row * KSTORE;
    *reinterpret_cast<ushort4*>(base + c4)       = hv;
    *reinterpret_cast<ushort4*>(base + 256 + c4) = lv;
}

// merged weight conversions + bias tables in ONE launch (grid = 1108 blocks):
//   [0,768):    qkv_w -> g_bq (q cols scaled)
//   [768,1024): proj_w -> g_bp
//   [1024,1105): rpb gather -> g_bias
//   [1105,1108): scaled qkv bias -> g_sbias
__global__ __launch_bounds__(256) void prep_wb_kernel(
    const float* __restrict__ qkv_w, const float* __restrict__ proj_w,
    const float* __restrict__ rpb, const int* __restrict__ rel,
    const float* __restrict__ qkv_b) {
    int blk = blockIdx.x;
    if (blk < 1024) {
        const float* w;
        __nv_bfloat16* Bext;
        int N, nscale, i;
        if (blk < 768) {
            w = qkv_w; Bext = g_bq; N = QKVN; nscale = DIM;
            i = blk * 256 + threadIdx.x;
        } else {
            w = proj_w; Bext = g_bp; N = DIM; nscale = 0;
            i = (blk - 768) * 256 + threadIdx.x;
        }
        int n = i >> 8, k = i & 255;
        float val = w[k * N + n];
        if (n < nscale) val *= SCALE;
        unsigned short h, l;
        bf_split(val, h, l);
        Bext[(size_t)n * KSTORE + k]       = __ushort_as_bfloat16(h);
        Bext[(size_t)n * KSTORE + 256 + k] = __ushort_as_bfloat16(l);
    } else if (blk < 1105) {
        int idx = (blk - 1024) * 256 + threadIdx.x;
        if (idx < NW * NW) {
            int r = rel[idx];
#pragma unroll
            for (int h = 0; h < NH; h++)
                g_bias[h * (NW * NW) + idx] = rpb[r * NH + h];
        }
    } else {
        int i = (blk - 1105) * 256 + threadIdx.x;
        if (i < QKVN) g_sbias[i] = qkv_b[i] * (i < DIM ? SCALE : 1.0f);
    }
}

// ======================= mma.sync GEMM: C = Aext @ Bext^T + bias =============
// grouped K: for g=0..7 load (Ah_g, Al_g, Bh_g, Bl_g) once; MMA terms
// Ah*Bh + Al*Bh + Ah*Bl with Ah fragments reused from registers.
#define SPITCH 80
#define STAGE_BYTES (128 * SPITCH)          /* 10240 per buffer */
#define SMEM_GEMM (8 * STAGE_BYTES)         /* 81920: 4 bufs x 2 stages */

template <bool PACK>
__global__ __launch_bounds__(256, 2) void gemm_mma_kernel(
    const __nv_bfloat16* __restrict__ Aext,
    const __nv_bfloat16* __restrict__ Bext,
    const float* __restrict__ bias,
    void* __restrict__ Cout, int Ntot) {
    extern __shared__ char gsm[];
    const uint32_t sAb = smem_u32(gsm);
    const uint32_t sBb = sAb + 4 * STAGE_BYTES;

    const int tid = threadIdx.x;
    const int w = tid >> 5, l = tid & 31;
    const int wm = w & 1, wn = w >> 1;
    const int tileN = blockIdx.x, tileM = blockIdx.y;

    const char* Ab = reinterpret_cast<const char*>(Aext) +
                     (size_t)tileM * 128 * (KSTORE * 2);
    const char* Bb = reinterpret_cast<const char*>(Bext) +
                     (size_t)tileN * 128 * (KSTORE * 2);

    const int lrow = tid >> 2;
    const int lseg = (tid & 3) * 16;

    float acc[4][4][4];
#pragma unroll
    for (int mf = 0; mf < 4; mf++)
#pragma unroll
        for (int nf = 0; nf < 4; nf++)
#pragma unroll
            for (int r = 0; r < 4; r++) acc[mf][nf][r] = 0.f;

#define ISSUE_GROUP(gg) do {                                                      \
        const int _g = (gg);                                                      \
        const uint32_t _sa = sAb + (uint32_t)(_g & 1) * (2 * STAGE_BYTES);        \
        const uint32_t _sb = sBb + (uint32_t)(_g & 1) * (2 * STAGE_BYTES);        \
        const size_t _r1 = (size_t)lrow * (KSTORE * 2);                           \
        const size_t _r2 = (size_t)(lrow + 64) * (KSTORE * 2);                    \
        const int _hc = _g * 64 + lseg;                                           \
        const int _lc = 512 + _g * 64 + lseg;                                     \
        CPASYNC16(_sa + lrow * SPITCH + lseg,              Ab + _r1 + _hc);       \
        CPASYNC16(_sa + (lrow + 64) * SPITCH + lseg,       Ab + _r2 + _hc);       \
        CPASYNC16(_sa + STAGE_BYTES + lrow * SPITCH + lseg,        Ab + _r1 + _lc); \
        CPASYNC16(_sa + STAGE_BYTES + (lrow + 64) * SPITCH + lseg, Ab + _r2 + _lc); \
        CPASYNC16(_sb + lrow * SPITCH + lseg,              Bb + _r1 + _hc);       \
        CPASYNC16(_sb + (lrow + 64) * SPITCH + lseg,       Bb + _r2 + _hc);       \
        CPASYNC16(_sb + STAGE_BYTES + lrow * SPITCH + lseg,        Bb + _r1 + _lc); \
        CPASYNC16(_sb + STAGE_BYTES + (lrow + 64) * SPITCH + lseg, Bb + _r2 + _lc); \
        CP_COMMIT();                                                              \
    } while (0)

    ISSUE_GROUP(0);
    ISSUE_GROUP(1);

    const uint32_t aRowOff = (uint32_t)(wm * 64 + (l & 15)) * SPITCH + (l >> 4) * 16;
    const uint32_t bRowOff = (uint32_t)(wn * 32 + ((l >> 4) * 8 + (l & 7))) * SPITCH +
                             ((l >> 3) & 1) * 16;

    for (int g = 0; g < 8; g++) {
        if (g < 7) CP_WAIT1(); else CP_WAIT0();
        __syncthreads();

        const uint32_t st = (uint32_t)(g & 1) * (2 * STAGE_BYTES);
        const uint32_t aH = sAb + st + aRowOff;
        const uint32_t aL = aH + STAGE_BYTES;
        const uint32_t bH = sBb + st + bRowOff;
        const uint32_t bL = bH + STAGE_BYTES;

#pragma unroll
        for (int ks = 0; ks < 2; ks++) {
            uint32_t ah[4][4], al[4][4], bf[2][4];
#pragma unroll
            for (int mf = 0; mf < 4; mf++)
                LDMX4(ah[mf][0], ah[mf][1], ah[mf][2], ah[mf][3],
                      aH + mf * (16 * SPITCH) + ks * 32);
#pragma unroll
            for (int n2 = 0; n2 < 2; n2++)
                LDMX4(bf[n2][0], bf[n2][1], bf[n2][2], bf[n2][3],
                      bH + n2 * (16 * SPITCH) + ks * 32);
#pragma unroll
            for (int mf = 0; mf < 4; mf++)
#pragma unroll
                for (int nf = 0; nf < 4; nf++)
                    MMA16816(acc[mf][nf], ah[mf],
                             bf[nf >> 1][(nf & 1) * 2],
                             bf[nf >> 1][(nf & 1) * 2 + 1]);
#pragma unroll
            for (int mf = 0; mf < 4; mf++)
                LDMX4(al[mf][0], al[mf][1], al[mf][2], al[mf][3],
                      aL + mf * (16 * SPITCH) + ks * 32);
#pragma unroll
            for (int mf = 0; mf < 4; mf++)
#pragma unroll
                for (int nf = 0; nf < 4; nf++)
                    MMA16816(acc[mf][nf], al[mf],
                             bf[nf >> 1][(nf & 1) * 2],
                             bf[nf >> 1][(nf & 1) * 2 + 1]);
#pragma unroll
            for (int n2 = 0; n2 < 2; n2++)
                LDMX4(bf[n2][0], bf[n2][1], bf[n2][2], bf[n2][3],
                      bL + n2 * (16 * SPITCH) + ks * 32);
#pragma unroll
            for (int mf = 0; mf < 4; mf++)
#pragma unroll
                for (int nf = 0; nf < 4; nf++)
                    MMA16816(acc[mf][nf], ah[mf],
                             bf[nf >> 1][(nf & 1) * 2],
                             bf[nf >> 1][(nf & 1) * 2 + 1]);
        }
        __syncthreads();
        if (g + 2 < 8) ISSUE_GROUP(g + 2);
    }
#undef ISSUE_GROUP

    const int rbase = tileM * 128 + wm * 64 + (l >> 2);
    const int cbase = tileN * 128 + wn * 32 + (l & 3) * 2;
#pragma unroll
    for (int mf = 0; mf < 4; mf++) {
#pragma unroll
        for (int nf = 0; nf < 4; nf++) {
            const int col = cbase + nf * 8;
            const float b0 = bias[col], b1 = bias[col + 1];
            const size_t r0 = (size_t)(rbase + mf * 16) * Ntot + col;
            const size_t r1 = r0 + (size_t)8 * Ntot;
            if (PACK) {
                uint32_t* C = reinterpret_cast<uint32_t*>(Cout);
                *reinterpret_cast<uint2*>(C + r0) =
                    make_uint2(pack_hl(acc[mf][nf][0] + b0), pack_hl(acc[mf][nf][1] + b1));
                *reinterpret_cast<uint2*>(C + r1) =
                    make_uint2(pack_hl(acc[mf][nf][2] + b0), pack_hl(acc[mf][nf][3] + b1));
            } else {
                float* C = reinterpret_cast<float*>(Cout);
                *reinterpret_cast<float2*>(C + r0) =
                    make_float2(acc[mf][nf][0] + b0, acc[mf][nf][1] + b1);
                *reinterpret_cast<float2*>(C + r1) =
                    make_float2(acc[mf][nf][2] + b0, acc[mf][nf][3] + b1);
            }
        }
    }
}

// ======================= tensor-core attention v3 ============================
// one block per (head, window): 288 threads = 9 warps; warp w owns query rows
// [w*16, w*16+16) across ALL 144 keys. Softmax is register+quad-shuffle only;
// PV produces complete O rows (no cross-warp reduction). ONE __syncthreads.
#define QPITCH 144
#define KPITCH 144
#define VPITCH 592
#define OFF_Q   0
#define OFF_K   (144 * QPITCH)            /* 20736 */
#define OFF_V   (OFF_K + 144 * KPITCH)    /* 41472 */
#define SMEM_ATTN (OFF_V + 32 * VPITCH)   /* 60416 */

__global__ __launch_bounds__(288, 1) void attn_tc_kernel() {
    extern __shared__ char sm[];
    const uint32_t sb = smem_u32(sm);
    const int tid = threadIdx.x, l = tid & 31, w = tid >> 5;
    const int h = blockIdx.x, b = blockIdx.y;
    const size_t tokBase = (size_t)b * NW;

    // ---- stage Q and K ----
    for (int idx = tid; idx < 144 * 8; idx += 288) {
        int r = idx >> 3, d4 = (idx & 7) * 4;
        uint4 q = *reinterpret_cast<const uint4*>(
            g_qkv + (tokBase + r) * QKVN + h * HD + d4);
        char* qb = sm + OFF_Q + r * QPITCH + d4 * 2;
        *reinterpret_cast<uint32_t*>(qb)      = __byte_perm(q.x, q.y, 0x5410);
        *reinterpret_cast<uint32_t*>(qb + 4)  = __byte_perm(q.z, q.w, 0x5410);
        *reinterpret_cast<uint32_t*>(qb + 64) = __byte_perm(q.x, q.y, 0x7632);
        *reinterpret_cast<uint32_t*>(qb + 68) = __byte_perm(q.z, q.w, 0x7632);
        uint4 k = *reinterpret_cast<const uint4*>(
            g_qkv + (tokBase + r) * QKVN + DIM + h * HD + d4);
        char* kb = sm + OFF_K + r * KPITCH + d4 * 2;
        *reinterpret_cast<uint32_t*>(kb)      = __byte_perm(k.x, k.y, 0x5410);
        *reinterpret_cast<uint32_t*>(kb + 4)  = __byte_perm(k.z, k.w, 0x5410);
        *reinterpret_cast<uint32_t*>(kb + 64) = __byte_perm(k.x, k.y, 0x7632);
        *reinterpret_cast<uint32_t*>(kb + 68) = __byte_perm(k.z, k.w, 0x7632);
    }
    // ---- stage V transposed ----
    for (int idx = tid; idx < 144 * 8; idx += 288) {
        int m = idx >> 3, d4 = (idx & 7) * 4;
        uint4 e = *reinterpret_cast<const uint4*>(
            g_qkv + (tokBase + m) * QKVN + 2 * DIM + h * HD + d4);
        uint32_t ev[4] = {e.x, e.y, e.z, e.w};
#pragma unroll
        for (int j = 0; j < 4; j++) {
            char* base = sm + OFF_V + (d4 + j) * VPITCH + 2 * m;
            *reinterpret_cast<unsigned short*>(base)       = (unsigned short)ev[j];
            *reinterpret_cast<unsigned short*>(base + 288) = (unsigned short)(ev[j] >> 16);
        }
    }
    __syncthreads();    // the only block barrier

    // ---- QK^T: S[16 x 144] per warp (3 split passes, k=32 each) ----
    float accS[18][4];
#pragma unroll
    for (int j = 0; j < 18; j++)
#pragma unroll
        for (int e = 0; e < 4; e++) accS[j][e] = 0.f;

    const uint32_t aBase = sb + OFF_Q + (w * 16 + (l & 15)) * QPITCH + (l >> 4) * 16;
    const uint32_t bBase = sb + OFF_K +
        (((l >> 4) & 1) * 8 + (l & 7)) * KPITCH + ((l >> 3) & 1) * 16;
#pragma unroll
    for (int pass = 0; pass < 3; pass++) {
        const int aoff = (pass == 1) ? 64 : 0;
        const int boff = (pass == 2) ? 64 : 0;
#pragma unroll
        for (int ks = 0; ks < 2; ks++) {
            uint32_t afr[4];
            LDMX4(afr[0], afr[1], afr[2], afr[3], aBase + aoff + ks * 32);
#pragma unroll
            for (int jp = 0; jp < 9; jp++) {
                uint32_t bfr[4];
                LDMX4(bfr[0], bfr[1], bfr[2], bfr[3],
                      bBase + jp * (16 * KPITCH) + boff + ks * 32);
                MMA16816(accS[jp * 2],     afr, bfr[0], bfr[1]);
                MMA16816(accS[jp * 2 + 1], afr, bfr[2], bfr[3]);
            }
        }
    }

    // ---- bias add + row max (register + quad shuffle only) ----
    const float* bh = g_bias + h * (NW * NW);
    const int r0 = w * 16 + (l >> 2);
    float rmax0 = -1e30f, rmax1 = -1e30f;
#pragma unroll
    for (int j = 0; j < 18; j++) {
        const int c = j * 8 + (l & 3) * 2;
        float2 b0 = *reinterpret_cast<const float2*>(bh + r0 * NW + c);
        float2 b1 = *reinterpret_cast<const float2*>(bh + (r0 + 8) * NW + c);
        accS[j][0] += b0.x; accS[j][1] += b0.y;
        accS[j][2] += b1.x; accS[j][3] += b1.y;
        rmax0 = fmaxf(rmax0, fmaxf(accS[j][0], accS[j][1]));
        rmax1 = fmaxf(rmax1, fmaxf(accS[j][2], accS[j][3]));
    }
#pragma unroll
    for (int o = 1; o <= 2; o <<= 1) {
        rmax0 = fmaxf(rmax0, __shfl_xor_sync(0xffffffff, rmax0, o));
        rmax1 = fmaxf(rmax1, __shfl_xor_sync(0xffffffff, rmax1, o));
    }

    // ---- exp + row sum ----
    float rsum0 = 0.f, rsum1 = 0.f;
#pragma unroll
    for (int j = 0; j < 18; j++) {
        accS[j][0] = __expf(accS[j][0] - rmax0);
        accS[j][1] = __expf(accS[j][1] - rmax0);
        accS[j][2] = __expf(accS[j][2] - rmax1);
        accS[j][3] = __expf(accS[j][3] - rmax1);
        rsum0 += accS[j][0] + accS[j][1];
        rsum1 += accS[j][2] + accS[j][3];
    }
#pragma unroll
    for (int o = 1; o <= 2; o <<= 1) {
        rsum0 += __shfl_xor_sync(0xffffffff, rsum0, o);
        rsum1 += __shfl_xor_sync(0xffffffff, rsum1, o);
    }
    const float inv0 = 1.0f / rsum0;
    const float inv1 = 1.0f / rsum1;

    // ---- normalize + build P A-fragments IN REGISTERS (hi & lo) ----
    uint32_t ph[9][4], pl[9][4];
#pragma unroll
    for (int kk = 0; kk < 9; kk++) {
        const int j0 = 2 * kk, j1 = 2 * kk + 1;
        split2(accS[j0][0] * inv0, accS[j0][1] * inv0, ph[kk][0], pl[kk][0]);
        split2(accS[j0][2] * inv1, accS[j0][3] * inv1, ph[kk][1], pl[kk][1]);
        split2(accS[j1][0] * inv0, accS[j1][1] * inv0, ph[kk][2], pl[kk][2]);
        split2(accS[j1][2] * inv1, accS[j1][3] * inv1, ph[kk][3], pl[kk][3]);
    }

    // ---- PV: complete O[16 x 32] per warp (3 split terms, k=144) ----
    float accO[4][4];
#pragma unroll
    for (int j = 0; j < 4; j++)
#pragma unroll
        for (int e = 0; e < 4; e++) accO[j][e] = 0.f;

    const uint32_t vBase = sb + OFF_V +
        (((l >> 4) & 1) * 8 + (l & 7)) * VPITCH + ((l >> 3) & 1) * 16;
#pragma unroll
    for (int kk = 0; kk < 9; kk++) {
        uint32_t vh[2][4], vl[2][4];
#pragma unroll
        for (int jp = 0; jp < 2; jp++)
            LDMX4(vh[jp][0], vh[jp][1], vh[jp][2], vh[jp][3],
                  vBase + jp * (16 * VPITCH) + kk * 32);
#pragma unroll
        for (int j = 0; j < 4; j++) {
            MMA16816(accO[j], ph[kk],
                     vh[j >> 1][(j & 1) * 2], vh[j >> 1][(j & 1) * 2 + 1]);
            MMA16816(accO[j], pl[kk],
                     vh[j >> 1][(j & 1) * 2], vh[j >> 1][(j & 1) * 2 + 1]);
        }
#pragma unroll
        for (int jp = 0; jp < 2; jp++)
            LDMX4(vl[jp][0], vl[jp][1], vl[jp][2], vl[jp][3],
                  vBase + jp * (16 * VPITCH) + kk * 32 + 288);
#pragma unroll
        for (int j = 0; j < 4; j++)
            MMA16816(accO[j], ph[kk],
                     vl[j >> 1][(j & 1) * 2], vl[j >> 1][(j & 1) * 2 + 1]);
    }

    // ---- write O ext [Oh|Ol] directly (no reduction needed) ----
#pragma unroll
    for (int j = 0; j < 4; j++) {
        const int cc = j * 8 + (l & 3) * 2;
        uint32_t hp0, lp0, hp1, lp1;
        split2(accO[j][0], accO[j][1], hp0, lp0);
        split2(accO[j][2], accO[j][3], hp1, lp1);
        __nv_bfloat16* o0 = g_attx + (tokBase + r0) * KSTORE + h * HD + cc;
        __nv_bfloat16* o1 = g_attx + (tokBase + r0 + 8) * KSTORE + h * HD + cc;
        *reinterpret_cast<uint32_t*>(o0)       = hp0;
        *reinterpret_cast<uint32_t*>(o0 + 256) = lp0;
        *reinterpret_cast<uint32_t*>(o1)       = hp1;
        *reinterpret_cast<uint32_t*>(o1 + 256) = lp1;
    }
}

// ---------------- launch ------------------------------------------------------
extern "C" void kernel_launch(void* const* d_in, const int* in_sizes, int n_in,
                              void* d_out, int out_size) {
    const float* x      = (const float*)d_in[0];
    const float* qkv_w  = (const float*)d_in[1];
    const float* qkv_b  = (const float*)d_in[2];
    const float* proj_w = (const float*)d_in[3];
    const float* proj_b = (const float*)d_in[4];
    const float* rpb    = (const float*)d_in[5];
    const int*   rel    = (const int*)d_in[6];

    uint32_t* qkvbuf = nullptr;
    __nv_bfloat16 *axp = nullptr, *attxp = nullptr, *bqp = nullptr, *bpp = nullptr;
    float* sbp = nullptr;
    cudaGetSymbolAddress((void**)&qkvbuf, g_qkv);
    cudaGetSymbolAddress((void**)&axp,   g_ax);
    cudaGetSymbolAddress((void**)&attxp, g_attx);
    cudaGetSymbolAddress((void**)&bqp,   g_bq);
    cudaGetSymbolAddress((void**)&bpp,   g_bp);
    cudaGetSymbolAddress((void**)&sbp,   g_sbias);

    static bool attr_done = false;
    if (!attr_done) {
        cudaFuncSetAttribute(attn_tc_kernel,
                             cudaFuncAttributeMaxDynamicSharedMemorySize, SMEM_ATTN);
        cudaFuncSetAttribute(gemm_mma_kernel<true>,
                             cudaFuncAttributeMaxDynamicSharedMemorySize, SMEM_GEMM);
        cudaFuncSetAttribute(gemm_mma_kernel<false>,
                             cudaFuncAttributeMaxDynamicSharedMemorySize, SMEM_GEMM);
        attr_done = true;
    }

    // order: profiled launch slot (index 3) = attention
    conv_x_kernel<<<(NTOK * 64) / 256, 256>>>(x);                    // 0
    prep_wb_kernel<<<1108, 256>>>(qkv_w, proj_w, rpb, rel, qkv_b);   // 1
    gemm_mma_kernel<true><<<dim3(QKVN / 128, NTOK / 128), 256, SMEM_GEMM>>>(
        axp, bqp, sbp, qkvbuf, QKVN);                                // 2
    attn_tc_kernel<<<dim3(NH, BnW), 288, SMEM_ATTN>>>();             // 3 <- profiled
    gemm_mma_kernel<false><<<dim3(DIM / 128, NTOK / 128), 256, SMEM_GEMM>>>(
        attxp, bpp, proj_b, d_out, DIM);                             // 4
}

// round 9
// speedup vs baseline: 1.3817x; 1.2161x over previous
#include <cuda_runtime.h>
#include <cuda_bf16.h>
#include <cstdint>
#include <cstddef>

#define BnW   2048
#define NW    144
#define DIM   256
#define NH    8
#define HD    32
#define NTOK  (BnW * NW)            /* 294912 */
#define QKVN  (3 * DIM)             /* 768 */
#define KSTORE 512                  /* split-bf16 stored K: [hi|lo] */
#define SCALE 0.17677669529663687f

// ---------------- scratch (device globals: allocation-free rule) -------------
__device__ uint32_t      g_qkv[(size_t)NTOK * QKVN];     // packed (hi|lo) bf16 q|k|v
__device__ __nv_bfloat16 g_ax[(size_t)NTOK * KSTORE];    // x ext [Ah|Al]
__device__ __nv_bfloat16 g_attx[(size_t)NTOK * KSTORE];  // attn out ext [Oh|Ol]
__device__ __nv_bfloat16 g_bq[(size_t)QKVN * KSTORE];    // qkv_w ext [Bh|Bl] (q-cols scaled)
__device__ __nv_bfloat16 g_bp[(size_t)DIM * KSTORE];     // proj_w ext
__device__ float         g_sbias[QKVN];                  // scaled qkv bias
__device__ float         g_bias[NH * NW * NW];           // [h][n][m] RPB

// ======================= baseline-PTX tensor-core helpers ====================
__device__ __forceinline__ uint32_t smem_u32(const void* p) {
    uint32_t a;
    asm("{ .reg .u64 t; cvta.to.shared.u64 t, %1; cvt.u32.u64 %0, t; }"
        : "=r"(a) : "l"(p));
    return a;
}
#define LDMX4(r0, r1, r2, r3, addr) \
    asm volatile("ldmatrix.sync.aligned.m8n8.x4.shared.b16 {%0,%1,%2,%3}, [%4];" \
                 : "=r"(r0), "=r"(r1), "=r"(r2), "=r"(r3) : "r"(addr))
#define MMA16816(d, a, b0, b1) \
    asm volatile("mma.sync.aligned.m16n8k16.row.col.f32.bf16.bf16.f32 " \
                 "{%0,%1,%2,%3}, {%4,%5,%6,%7}, {%8,%9}, {%0,%1,%2,%3};" \
                 : "+f"((d)[0]), "+f"((d)[1]), "+f"((d)[2]), "+f"((d)[3]) \
                 : "r"((a)[0]), "r"((a)[1]), "r"((a)[2]), "r"((a)[3]), \
                   "r"(b0), "r"(b1))
#define CPASYNC16(s, g) \
    asm volatile("cp.async.cg.shared.global [%0], [%1], 16;" :: "r"(s), "l"(g))
#define CP_COMMIT() asm volatile("cp.async.commit_group;" ::: "memory")
#define CP_WAIT1()  asm volatile("cp.async.wait_group 1;" ::: "memory")
#define CP_WAIT0()  asm volatile("cp.async.wait_group 0;" ::: "memory")

// ======================= split-bf16 helpers ==================================
__device__ __forceinline__ void bf_split(float f, unsigned short& h, unsigned short& l) {
    __nv_bfloat16 hb = __float2bfloat16(f);
    __nv_bfloat16 lb = __float2bfloat16(f - __bfloat162float(hb));
    h = __bfloat16_as_ushort(hb);
    l = __bfloat16_as_ushort(lb);
}
__device__ __forceinline__ uint32_t pack_hl(float f) {
    unsigned short h, l;
    bf_split(f, h, l);
    return (uint32_t)h | ((uint32_t)l << 16);
}
__device__ __forceinline__ void split2(float x, float y, uint32_t& hp, uint32_t& lp) {
    unsigned short hx, lx, hy, ly;
    bf_split(x, hx, lx);
    bf_split(y, hy, ly);
    hp = (uint32_t)hx | ((uint32_t)hy << 16);
    lp = (uint32_t)lx | ((uint32_t)ly << 16);
}

// x [NTOK,256] fp32 -> g_ax [NTOK,512] = [Ah|Al]
__global__ __launch_bounds__(256) void conv_x_kernel(const float* __restrict__ x) {
    size_t i = (size_t)blockIdx.x * 256 + threadIdx.x;   // over NTOK*64
    size_t row = i >> 6;
    int c4 = (int)(i & 63) * 4;
    float4 v = *reinterpret_cast<const float4*>(x + row * DIM + c4);
    ushort4 hv, lv;
    bf_split(v.x, hv.x, lv.x); bf_split(v.y, hv.y, lv.y);
    bf_split(v.z, hv.z, lv.z); bf_split(v.w, hv.w, lv.w);
    __nv_bfloat16* base = g_ax + row * KSTORE;
    *reinterpret_cast<ushort4*>(base + c4)       = hv;
    *reinterpret_cast<ushort4*>(base + 256 + c4) = lv;
}

// merged weight conversions + bias tables in ONE launch (grid = 1108 blocks)
__global__ __launch_bounds__(256) void prep_wb_kernel(
    const float* __restrict__ qkv_w, const float* __restrict__ proj_w,
    const float* __restrict__ rpb, const int* __restrict__ rel,
    const float* __restrict__ qkv_b) {
    int blk = blockIdx.x;
    if (blk < 1024) {
        const float* w;
        __nv_bfloat16* Bext;
        int N, nscale, i;
        if (blk < 768) {
            w = qkv_w; Bext = g_bq; N = QKVN; nscale = DIM;
            i = blk * 256 + threadIdx.x;
        } else {
            w = proj_w; Bext = g_bp; N = DIM; nscale = 0;
            i = (blk - 768) * 256 + threadIdx.x;
        }
        int n = i >> 8, k = i & 255;
        float val = w[k * N + n];
        if (n < nscale) val *= SCALE;
        unsigned short h, l;
        bf_split(val, h, l);
        Bext[(size_t)n * KSTORE + k]       = __ushort_as_bfloat16(h);
        Bext[(size_t)n * KSTORE + 256 + k] = __ushort_as_bfloat16(l);
    } else if (blk < 1105) {
        int idx = (blk - 1024) * 256 + threadIdx.x;
        if (idx < NW * NW) {
            int r = rel[idx];
#pragma unroll
            for (int h = 0; h < NH; h++)
                g_bias[h * (NW * NW) + idx] = rpb[r * NH + h];
        }
    } else {
        int i = (blk - 1105) * 256 + threadIdx.x;
        if (i < QKVN) g_sbias[i] = qkv_b[i] * (i < DIM ? SCALE : 1.0f);
    }
}

// ======================= mma.sync GEMM: C = Aext @ Bext^T + bias =============
#define SPITCH 80
#define STAGE_BYTES (128 * SPITCH)          /* 10240 per buffer */
#define SMEM_GEMM (8 * STAGE_BYTES)         /* 81920: 4 bufs x 2 stages */

template <bool PACK>
__global__ __launch_bounds__(256, 2) void gemm_mma_kernel(
    const __nv_bfloat16* __restrict__ Aext,
    const __nv_bfloat16* __restrict__ Bext,
    const float* __restrict__ bias,
    void* __restrict__ Cout, int Ntot) {
    extern __shared__ char gsm[];
    const uint32_t sAb = smem_u32(gsm);
    const uint32_t sBb = sAb + 4 * STAGE_BYTES;

    const int tid = threadIdx.x;
    const int w = tid >> 5, l = tid & 31;
    const int wm = w & 1, wn = w >> 1;
    const int tileN = blockIdx.x, tileM = blockIdx.y;

    const char* Ab = reinterpret_cast<const char*>(Aext) +
                     (size_t)tileM * 128 * (KSTORE * 2);
    const char* Bb = reinterpret_cast<const char*>(Bext) +
                     (size_t)tileN * 128 * (KSTORE * 2);

    const int lrow = tid >> 2;
    const int lseg = (tid & 3) * 16;

    float acc[4][4][4];
#pragma unroll
    for (int mf = 0; mf < 4; mf++)
#pragma unroll
        for (int nf = 0; nf < 4; nf++)
#pragma unroll
            for (int r = 0; r < 4; r++) acc[mf][nf][r] = 0.f;

#define ISSUE_GROUP(gg) do {                                                      \
        const int _g = (gg);                                                      \
        const uint32_t _sa = sAb + (uint32_t)(_g & 1) * (2 * STAGE_BYTES);        \
        const uint32_t _sb = sBb + (uint32_t)(_g & 1) * (2 * STAGE_BYTES);        \
        const size_t _r1 = (size_t)lrow * (KSTORE * 2);                           \
        const size_t _r2 = (size_t)(lrow + 64) * (KSTORE * 2);                    \
        const int _hc = _g * 64 + lseg;                                           \
        const int _lc = 512 + _g * 64 + lseg;                                     \
        CPASYNC16(_sa + lrow * SPITCH + lseg,              Ab + _r1 + _hc);       \
        CPASYNC16(_sa + (lrow + 64) * SPITCH + lseg,       Ab + _r2 + _hc);       \
        CPASYNC16(_sa + STAGE_BYTES + lrow * SPITCH + lseg,        Ab + _r1 + _lc); \
        CPASYNC16(_sa + STAGE_BYTES + (lrow + 64) * SPITCH + lseg, Ab + _r2 + _lc); \
        CPASYNC16(_sb + lrow * SPITCH + lseg,              Bb + _r1 + _hc);       \
        CPASYNC16(_sb + (lrow + 64) * SPITCH + lseg,       Bb + _r2 + _hc);       \
        CPASYNC16(_sb + STAGE_BYTES + lrow * SPITCH + lseg,        Bb + _r1 + _lc); \
        CPASYNC16(_sb + STAGE_BYTES + (lrow + 64) * SPITCH + lseg, Bb + _r2 + _lc); \
        CP_COMMIT();                                                              \
    } while (0)

    ISSUE_GROUP(0);
    ISSUE_GROUP(1);

    const uint32_t aRowOff = (uint32_t)(wm * 64 + (l & 15)) * SPITCH + (l >> 4) * 16;
    const uint32_t bRowOff = (uint32_t)(wn * 32 + ((l >> 4) * 8 + (l & 7))) * SPITCH +
                             ((l >> 3) & 1) * 16;

    for (int g = 0; g < 8; g++) {
        if (g < 7) CP_WAIT1(); else CP_WAIT0();
        __syncthreads();

        const uint32_t st = (uint32_t)(g & 1) * (2 * STAGE_BYTES);
        const uint32_t aH = sAb + st + aRowOff;
        const uint32_t aL = aH + STAGE_BYTES;
        const uint32_t bH = sBb + st + bRowOff;
        const uint32_t bL = bH + STAGE_BYTES;

#pragma unroll
        for (int ks = 0; ks < 2; ks++) {
            uint32_t ah[4][4], al[4][4], bf[2][4];
#pragma unroll
            for (int mf = 0; mf < 4; mf++)
                LDMX4(ah[mf][0], ah[mf][1], ah[mf][2], ah[mf][3],
                      aH + mf * (16 * SPITCH) + ks * 32);
#pragma unroll
            for (int n2 = 0; n2 < 2; n2++)
                LDMX4(bf[n2][0], bf[n2][1], bf[n2][2], bf[n2][3],
                      bH + n2 * (16 * SPITCH) + ks * 32);
#pragma unroll
            for (int mf = 0; mf < 4; mf++)
#pragma unroll
                for (int nf = 0; nf < 4; nf++)
                    MMA16816(acc[mf][nf], ah[mf],
                             bf[nf >> 1][(nf & 1) * 2],
                             bf[nf >> 1][(nf & 1) * 2 + 1]);
#pragma unroll
            for (int mf = 0; mf < 4; mf++)
                LDMX4(al[mf][0], al[mf][1], al[mf][2], al[mf][3],
                      aL + mf * (16 * SPITCH) + ks * 32);
#pragma unroll
            for (int mf = 0; mf < 4; mf++)
#pragma unroll
                for (int nf = 0; nf < 4; nf++)
                    MMA16816(acc[mf][nf], al[mf],
                             bf[nf >> 1][(nf & 1) * 2],
                             bf[nf >> 1][(nf & 1) * 2 + 1]);
#pragma unroll
            for (int n2 = 0; n2 < 2; n2++)
                LDMX4(bf[n2][0], bf[n2][1], bf[n2][2], bf[n2][3],
                      bL + n2 * (16 * SPITCH) + ks * 32);
#pragma unroll
            for (int mf = 0; mf < 4; mf++)
#pragma unroll
                for (int nf = 0; nf < 4; nf++)
                    MMA16816(acc[mf][nf], ah[mf],
                             bf[nf >> 1][(nf & 1) * 2],
                             bf[nf >> 1][(nf & 1) * 2 + 1]);
        }
        __syncthreads();
        if (g + 2 < 8) ISSUE_GROUP(g + 2);
    }
#undef ISSUE_GROUP

    const int rbase = tileM * 128 + wm * 64 + (l >> 2);
    const int cbase = tileN * 128 + wn * 32 + (l & 3) * 2;
#pragma unroll
    for (int mf = 0; mf < 4; mf++) {
#pragma unroll
        for (int nf = 0; nf < 4; nf++) {
            const int col = cbase + nf * 8;
            const float b0 = bias[col], b1 = bias[col + 1];
            const size_t r0 = (size_t)(rbase + mf * 16) * Ntot + col;
            const size_t r1 = r0 + (size_t)8 * Ntot;
            if (PACK) {
                uint32_t* C = reinterpret_cast<uint32_t*>(Cout);
                *reinterpret_cast<uint2*>(C + r0) =
                    make_uint2(pack_hl(acc[mf][nf][0] + b0), pack_hl(acc[mf][nf][1] + b1));
                *reinterpret_cast<uint2*>(C + r1) =
                    make_uint2(pack_hl(acc[mf][nf][2] + b0), pack_hl(acc[mf][nf][3] + b1));
            } else {
                float* C = reinterpret_cast<float*>(Cout);
                *reinterpret_cast<float2*>(C + r0) =
                    make_float2(acc[mf][nf][0] + b0, acc[mf][nf][1] + b1);
                *reinterpret_cast<float2*>(C + r1) =
                    make_float2(acc[mf][nf][2] + b0, acc[mf][nf][3] + b1);
            }
        }
    }
}

// ======================= tensor-core attention v4 ============================
// warp w owns query rows [w*16, w*16+16) across all 144 keys. P-fragment
// conversion is folded INTO the PV loop (per-chunk) so accS and the P
// fragments never coexist -> ~112 regs -> 2 CTAs/SM.
#define QPITCH 144
#define KPITCH 144
#define VPITCH 592
#define OFF_Q   0
#define OFF_K   (144 * QPITCH)            /* 20736 */
#define OFF_V   (OFF_K + 144 * KPITCH)    /* 41472 */
#define SMEM_ATTN (OFF_V + 32 * VPITCH)   /* 60416 */

__global__ __launch_bounds__(288, 2) void attn_tc_kernel() {
    extern __shared__ char sm[];
    const uint32_t sb = smem_u32(sm);
    const int tid = threadIdx.x, l = tid & 31, w = tid >> 5;
    const int h = blockIdx.x, b = blockIdx.y;
    const size_t tokBase = (size_t)b * NW;

    // ---- stage Q and K ----
    for (int idx = tid; idx < 144 * 8; idx += 288) {
        int r = idx >> 3, d4 = (idx & 7) * 4;
        uint4 q = *reinterpret_cast<const uint4*>(
            g_qkv + (tokBase + r) * QKVN + h * HD + d4);
        char* qb = sm + OFF_Q + r * QPITCH + d4 * 2;
        *reinterpret_cast<uint32_t*>(qb)      = __byte_perm(q.x, q.y, 0x5410);
        *reinterpret_cast<uint32_t*>(qb + 4)  = __byte_perm(q.z, q.w, 0x5410);
        *reinterpret_cast<uint32_t*>(qb + 64) = __byte_perm(q.x, q.y, 0x7632);
        *reinterpret_cast<uint32_t*>(qb + 68) = __byte_perm(q.z, q.w, 0x7632);
        uint4 k = *reinterpret_cast<const uint4*>(
            g_qkv + (tokBase + r) * QKVN + DIM + h * HD + d4);
        char* kb = sm + OFF_K + r * KPITCH + d4 * 2;
        *reinterpret_cast<uint32_t*>(kb)      = __byte_perm(k.x, k.y, 0x5410);
        *reinterpret_cast<uint32_t*>(kb + 4)  = __byte_perm(k.z, k.w, 0x5410);
        *reinterpret_cast<uint32_t*>(kb + 64) = __byte_perm(k.x, k.y, 0x7632);
        *reinterpret_cast<uint32_t*>(kb + 68) = __byte_perm(k.z, k.w, 0x7632);
    }
    // ---- stage V transposed ----
    for (int idx = tid; idx < 144 * 8; idx += 288) {
        int m = idx >> 3, d4 = (idx & 7) * 4;
        uint4 e = *reinterpret_cast<const uint4*>(
            g_qkv + (tokBase + m) * QKVN + 2 * DIM + h * HD + d4);
        uint32_t ev[4] = {e.x, e.y, e.z, e.w};
#pragma unroll
        for (int j = 0; j < 4; j++) {
            char* base = sm + OFF_V + (d4 + j) * VPITCH + 2 * m;
            *reinterpret_cast<unsigned short*>(base)       = (unsigned short)ev[j];
            *reinterpret_cast<unsigned short*>(base + 288) = (unsigned short)(ev[j] >> 16);
        }
    }
    __syncthreads();    // the only block barrier

    // ---- QK^T: S[16 x 144] per warp (3 split passes, k=32 each) ----
    float accS[18][4];
#pragma unroll
    for (int j = 0; j < 18; j++)
#pragma unroll
        for (int e = 0; e < 4; e++) accS[j][e] = 0.f;

    const uint32_t aBase = sb + OFF_Q + (w * 16 + (l & 15)) * QPITCH + (l >> 4) * 16;
    const uint32_t bBase = sb + OFF_K +
        (((l >> 4) & 1) * 8 + (l & 7)) * KPITCH + ((l >> 3) & 1) * 16;
#pragma unroll
    for (int pass = 0; pass < 3; pass++) {
        const int aoff = (pass == 1) ? 64 : 0;
        const int boff = (pass == 2) ? 64 : 0;
#pragma unroll
        for (int ks = 0; ks < 2; ks++) {
            uint32_t afr[4];
            LDMX4(afr[0], afr[1], afr[2], afr[3], aBase + aoff + ks * 32);
#pragma unroll
            for (int jp = 0; jp < 9; jp++) {
                uint32_t bfr[4];
                LDMX4(bfr[0], bfr[1], bfr[2], bfr[3],
                      bBase + jp * (16 * KPITCH) + boff + ks * 32);
                MMA16816(accS[jp * 2],     afr, bfr[0], bfr[1]);
                MMA16816(accS[jp * 2 + 1], afr, bfr[2], bfr[3]);
            }
        }
    }

    // ---- bias add + row max (register + quad shuffle only) ----
    const float* bh = g_bias + h * (NW * NW);
    const int r0 = w * 16 + (l >> 2);
    float rmax0 = -1e30f, rmax1 = -1e30f;
#pragma unroll
    for (int j = 0; j < 18; j++) {
        const int c = j * 8 + (l & 3) * 2;
        float2 b0 = *reinterpret_cast<const float2*>(bh + r0 * NW + c);
        float2 b1 = *reinterpret_cast<const float2*>(bh + (r0 + 8) * NW + c);
        accS[j][0] += b0.x; accS[j][1] += b0.y;
        accS[j][2] += b1.x; accS[j][3] += b1.y;
        rmax0 = fmaxf(rmax0, fmaxf(accS[j][0], accS[j][1]));
        rmax1 = fmaxf(rmax1, fmaxf(accS[j][2], accS[j][3]));
    }
#pragma unroll
    for (int o = 1; o <= 2; o <<= 1) {
        rmax0 = fmaxf(rmax0, __shfl_xor_sync(0xffffffff, rmax0, o));
        rmax1 = fmaxf(rmax1, __shfl_xor_sync(0xffffffff, rmax1, o));
    }

    // ---- exp + row sum ----
    float rsum0 = 0.f, rsum1 = 0.f;
#pragma unroll
    for (int j = 0; j < 18; j++) {
        accS[j][0] = __expf(accS[j][0] - rmax0);
        accS[j][1] = __expf(accS[j][1] - rmax0);
        accS[j][2] = __expf(accS[j][2] - rmax1);
        accS[j][3] = __expf(accS[j][3] - rmax1);
        rsum0 += accS[j][0] + accS[j][1];
        rsum1 += accS[j][2] + accS[j][3];
    }
#pragma unroll
    for (int o = 1; o <= 2; o <<= 1) {
        rsum0 += __shfl_xor_sync(0xffffffff, rsum0, o);
        rsum1 += __shfl_xor_sync(0xffffffff, rsum1, o);
    }
    const float inv0 = 1.0f / rsum0;
    const float inv1 = 1.0f / rsum1;

    // ---- PV with inline P conversion: per kk-chunk the P fragment is built
    //      from accS (which then dies) and consumed immediately. ----
    float accO[4][4];
#pragma unroll
    for (int j = 0; j < 4; j++)
#pragma unroll
        for (int e = 0; e < 4; e++) accO[j][e] = 0.f;

    const uint32_t vBase = sb + OFF_V +
        (((l >> 4) & 1) * 8 + (l & 7)) * VPITCH + ((l >> 3) & 1) * 16;
#pragma unroll
    for (int kk = 0; kk < 9; kk++) {
        uint32_t ph[4], pl[4];
        {
            const int j0 = 2 * kk, j1 = 2 * kk + 1;
            split2(accS[j0][0] * inv0, accS[j0][1] * inv0, ph[0], pl[0]);
            split2(accS[j0][2] * inv1, accS[j0][3] * inv1, ph[1], pl[1]);
            split2(accS[j1][0] * inv0, accS[j1][1] * inv0, ph[2], pl[2]);
            split2(accS[j1][2] * inv1, accS[j1][3] * inv1, ph[3], pl[3]);
        }
        uint32_t vf[2][4];
#pragma unroll
        for (int jp = 0; jp < 2; jp++)
            LDMX4(vf[jp][0], vf[jp][1], vf[jp][2], vf[jp][3],
                  vBase + jp * (16 * VPITCH) + kk * 32);
#pragma unroll
        for (int j = 0; j < 4; j++) {
            MMA16816(accO[j], ph,
                     vf[j >> 1][(j & 1) * 2], vf[j >> 1][(j & 1) * 2 + 1]);
            MMA16816(accO[j], pl,
                     vf[j >> 1][(j & 1) * 2], vf[j >> 1][(j & 1) * 2 + 1]);
        }
#pragma unroll
        for (int jp = 0; jp < 2; jp++)
            LDMX4(vf[jp][0], vf[jp][1], vf[jp][2], vf[jp][3],
                  vBase + jp * (16 * VPITCH) + kk * 32 + 288);
#pragma unroll
        for (int j = 0; j < 4; j++)
            MMA16816(accO[j], ph,
                     vf[j >> 1][(j & 1) * 2], vf[j >> 1][(j & 1) * 2 + 1]);
    }

    // ---- write O ext [Oh|Ol] directly ----
#pragma unroll
    for (int j = 0; j < 4; j++) {
        const int cc = j * 8 + (l & 3) * 2;
        uint32_t hp0, lp0, hp1, lp1;
        split2(accO[j][0], accO[j][1], hp0, lp0);
        split2(accO[j][2], accO[j][3], hp1, lp1);
        __nv_bfloat16* o0 = g_attx + (tokBase + r0) * KSTORE + h * HD + cc;
        __nv_bfloat16* o1 = g_attx + (tokBase + r0 + 8) * KSTORE + h * HD + cc;
        *reinterpret_cast<uint32_t*>(o0)       = hp0;
        *reinterpret_cast<uint32_t*>(o0 + 256) = lp0;
        *reinterpret_cast<uint32_t*>(o1)       = hp1;
        *reinterpret_cast<uint32_t*>(o1 + 256) = lp1;
    }
}

// ---------------- launch ------------------------------------------------------
extern "C" void kernel_launch(void* const* d_in, const int* in_sizes, int n_in,
                              void* d_out, int out_size) {
    const float* x      = (const float*)d_in[0];
    const float* qkv_w  = (const float*)d_in[1];
    const float* qkv_b  = (const float*)d_in[2];
    const float* proj_w = (const float*)d_in[3];
    const float* proj_b = (const float*)d_in[4];
    const float* rpb    = (const float*)d_in[5];
    const int*   rel    = (const int*)d_in[6];

    uint32_t* qkvbuf = nullptr;
    __nv_bfloat16 *axp = nullptr, *attxp = nullptr, *bqp = nullptr, *bpp = nullptr;
    float* sbp = nullptr;
    cudaGetSymbolAddress((void**)&qkvbuf, g_qkv);
    cudaGetSymbolAddress((void**)&axp,   g_ax);
    cudaGetSymbolAddress((void**)&attxp, g_attx);
    cudaGetSymbolAddress((void**)&bqp,   g_bq);
    cudaGetSymbolAddress((void**)&bpp,   g_bp);
    cudaGetSymbolAddress((void**)&sbp,   g_sbias);

    static bool attr_done = false;
    if (!attr_done) {
        cudaFuncSetAttribute(attn_tc_kernel,
                             cudaFuncAttributeMaxDynamicSharedMemorySize, SMEM_ATTN);
        cudaFuncSetAttribute(gemm_mma_kernel<true>,
                             cudaFuncAttributeMaxDynamicSharedMemorySize, SMEM_GEMM);
        cudaFuncSetAttribute(gemm_mma_kernel<false>,
                             cudaFuncAttributeMaxDynamicSharedMemorySize, SMEM_GEMM);
        attr_done = true;
    }

    // order: profiled launch slot (index 3) = attention
    conv_x_kernel<<<(NTOK * 64) / 256, 256>>>(x);                    // 0
    prep_wb_kernel<<<1108, 256>>>(qkv_w, proj_w, rpb, rel, qkv_b);   // 1
    gemm_mma_kernel<true><<<dim3(QKVN / 128, NTOK / 128), 256, SMEM_GEMM>>>(
        axp, bqp, sbp, qkvbuf, QKVN);                                // 2
    attn_tc_kernel<<<dim3(NH, BnW), 288, SMEM_ATTN>>>();             // 3 <- profiled
    gemm_mma_kernel<false><<<dim3(DIM / 128, NTOK / 128), 256, SMEM_GEMM>>>(
        attxp, bpp, proj_b, d_out, DIM);                             // 4
}

// round 10
// speedup vs baseline: 1.4774x; 1.0692x over previous
#include <cuda_runtime.h>
#include <cuda_bf16.h>
#include <cstdint>
#include <cstddef>

#define BnW   2048
#define NW    144
#define DIM   256
#define NH    8
#define HD    32
#define NTOK  (BnW * NW)            /* 294912 */
#define QKVN  (3 * DIM)             /* 768 */
#define KSTORE 512                  /* split-bf16 stored K: [hi|lo] */
#define SCALE 0.17677669529663687f

// ---------------- scratch (device globals: allocation-free rule) -------------
__device__ uint32_t      g_qkv[(size_t)NTOK * QKVN];     // packed (hi|lo) bf16 q|k|v
__device__ __nv_bfloat16 g_ax[(size_t)NTOK * KSTORE];    // x ext [Ah|Al]
__device__ __nv_bfloat16 g_attx[(size_t)NTOK * KSTORE];  // attn out ext [Oh|Ol]
__device__ __nv_bfloat16 g_bq[(size_t)QKVN * KSTORE];    // qkv_w ext [Bh|Bl] (q-cols scaled)
__device__ __nv_bfloat16 g_bp[(size_t)DIM * KSTORE];     // proj_w ext
__device__ float         g_sbias[QKVN];                  // scaled qkv bias
__device__ float         g_bias[NH * NW * NW];           // [h][n][m] RPB

// ======================= baseline-PTX tensor-core helpers ====================
__device__ __forceinline__ uint32_t smem_u32(const void* p) {
    uint32_t a;
    asm("{ .reg .u64 t; cvta.to.shared.u64 t, %1; cvt.u32.u64 %0, t; }"
        : "=r"(a) : "l"(p));
    return a;
}
#define LDMX4(r0, r1, r2, r3, addr) \
    asm volatile("ldmatrix.sync.aligned.m8n8.x4.shared.b16 {%0,%1,%2,%3}, [%4];" \
                 : "=r"(r0), "=r"(r1), "=r"(r2), "=r"(r3) : "r"(addr))
#define LDMX4T(r0, r1, r2, r3, addr) \
    asm volatile("ldmatrix.sync.aligned.m8n8.x4.trans.shared.b16 {%0,%1,%2,%3}, [%4];" \
                 : "=r"(r0), "=r"(r1), "=r"(r2), "=r"(r3) : "r"(addr))
#define MMA16816(d, a, b0, b1) \
    asm volatile("mma.sync.aligned.m16n8k16.row.col.f32.bf16.bf16.f32 " \
                 "{%0,%1,%2,%3}, {%4,%5,%6,%7}, {%8,%9}, {%0,%1,%2,%3};" \
                 : "+f"((d)[0]), "+f"((d)[1]), "+f"((d)[2]), "+f"((d)[3]) \
                 : "r"((a)[0]), "r"((a)[1]), "r"((a)[2]), "r"((a)[3]), \
                   "r"(b0), "r"(b1))
#define CPASYNC16(s, g) \
    asm volatile("cp.async.cg.shared.global [%0], [%1], 16;" :: "r"(s), "l"(g))
#define CP_COMMIT() asm volatile("cp.async.commit_group;" ::: "memory")
#define CP_WAIT1()  asm volatile("cp.async.wait_group 1;" ::: "memory")
#define CP_WAIT0()  asm volatile("cp.async.wait_group 0;" ::: "memory")

// ======================= split-bf16 helpers ==================================
__device__ __forceinline__ void bf_split(float f, unsigned short& h, unsigned short& l) {
    __nv_bfloat16 hb = __float2bfloat16(f);
    __nv_bfloat16 lb = __float2bfloat16(f - __bfloat162float(hb));
    h = __bfloat16_as_ushort(hb);
    l = __bfloat16_as_ushort(lb);
}
__device__ __forceinline__ uint32_t pack_hl(float f) {
    unsigned short h, l;
    bf_split(f, h, l);
    return (uint32_t)h | ((uint32_t)l << 16);
}
__device__ __forceinline__ void split2(float x, float y, uint32_t& hp, uint32_t& lp) {
    unsigned short hx, lx, hy, ly;
    bf_split(x, hx, lx);
    bf_split(y, hy, ly);
    hp = (uint32_t)hx | ((uint32_t)hy << 16);
    lp = (uint32_t)lx | ((uint32_t)ly << 16);
}

// x [NTOK,256] fp32 -> g_ax [NTOK,512] = [Ah|Al]
__global__ __launch_bounds__(256) void conv_x_kernel(const float* __restrict__ x) {
    size_t i = (size_t)blockIdx.x * 256 + threadIdx.x;   // over NTOK*64
    size_t row = i >> 6;
    int c4 = (int)(i & 63) * 4;
    float4 v = *reinterpret_cast<const float4*>(x + row * DIM + c4);
    ushort4 hv, lv;
    bf_split(v.x, hv.x, lv.x); bf_split(v.y, hv.y, lv.y);
    bf_split(v.z, hv.z, lv.z); bf_split(v.w, hv.w, lv.w);
    __nv_bfloat16* base = g_ax + row * KSTORE;
    *reinterpret_cast<ushort4*>(base + c4)       = hv;
    *reinterpret_cast<ushort4*>(base + 256 + c4) = lv;
}

// merged weight conversions + bias tables in ONE launch (grid = 1108 blocks)
__global__ __launch_bounds__(256) void prep_wb_kernel(
    const float* __restrict__ qkv_w, const float* __restrict__ proj_w,
    const float* __restrict__ rpb, const int* __restrict__ rel,
    const float* __restrict__ qkv_b) {
    int blk = blockIdx.x;
    if (blk < 1024) {
        const float* w;
        __nv_bfloat16* Bext;
        int N, nscale, i;
        if (blk < 768) {
            w = qkv_w; Bext = g_bq; N = QKVN; nscale = DIM;
            i = blk * 256 + threadIdx.x;
        } else {
            w = proj_w; Bext = g_bp; N = DIM; nscale = 0;
            i = (blk - 768) * 256 + threadIdx.x;
        }
        int n = i >> 8, k = i & 255;
        float val = w[k * N + n];
        if (n < nscale) val *= SCALE;
        unsigned short h, l;
        bf_split(val, h, l);
        Bext[(size_t)n * KSTORE + k]       = __ushort_as_bfloat16(h);
        Bext[(size_t)n * KSTORE + 256 + k] = __ushort_as_bfloat16(l);
    } else if (blk < 1105) {
        int idx = (blk - 1024) * 256 + threadIdx.x;
        if (idx < NW * NW) {
            int r = rel[idx];
#pragma unroll
            for (int h = 0; h < NH; h++)
                g_bias[h * (NW * NW) + idx] = rpb[r * NH + h];
        }
    } else {
        int i = (blk - 1105) * 256 + threadIdx.x;
        if (i < QKVN) g_sbias[i] = qkv_b[i] * (i < DIM ? SCALE : 1.0f);
    }
}

// ======================= mma.sync GEMM: C = Aext @ Bext^T + bias =============
#define SPITCH 80
#define STAGE_BYTES (128 * SPITCH)          /* 10240 per buffer */
#define SMEM_GEMM (8 * STAGE_BYTES)         /* 81920: 4 bufs x 2 stages */

template <bool PACK>
__global__ __launch_bounds__(256, 2) void gemm_mma_kernel(
    const __nv_bfloat16* __restrict__ Aext,
    const __nv_bfloat16* __restrict__ Bext,
    const float* __restrict__ bias,
    void* __restrict__ Cout, int Ntot) {
    extern __shared__ char gsm[];
    const uint32_t sAb = smem_u32(gsm);
    const uint32_t sBb = sAb + 4 * STAGE_BYTES;

    const int tid = threadIdx.x;
    const int w = tid >> 5, l = tid & 31;
    const int wm = w & 1, wn = w >> 1;
    const int tileN = blockIdx.x, tileM = blockIdx.y;

    const char* Ab = reinterpret_cast<const char*>(Aext) +
                     (size_t)tileM * 128 * (KSTORE * 2);
    const char* Bb = reinterpret_cast<const char*>(Bext) +
                     (size_t)tileN * 128 * (KSTORE * 2);

    const int lrow = tid >> 2;
    const int lseg = (tid & 3) * 16;

    float acc[4][4][4];
#pragma unroll
    for (int mf = 0; mf < 4; mf++)
#pragma unroll
        for (int nf = 0; nf < 4; nf++)
#pragma unroll
            for (int r = 0; r < 4; r++) acc[mf][nf][r] = 0.f;

#define ISSUE_GROUP(gg) do {                                                      \
        const int _g = (gg);                                                      \
        const uint32_t _sa = sAb + (uint32_t)(_g & 1) * (2 * STAGE_BYTES);        \
        const uint32_t _sb = sBb + (uint32_t)(_g & 1) * (2 * STAGE_BYTES);        \
        const size_t _r1 = (size_t)lrow * (KSTORE * 2);                           \
        const size_t _r2 = (size_t)(lrow + 64) * (KSTORE * 2);                    \
        const int _hc = _g * 64 + lseg;                                           \
        const int _lc = 512 + _g * 64 + lseg;                                     \
        CPASYNC16(_sa + lrow * SPITCH + lseg,              Ab + _r1 + _hc);       \
        CPASYNC16(_sa + (lrow + 64) * SPITCH + lseg,       Ab + _r2 + _hc);       \
        CPASYNC16(_sa + STAGE_BYTES + lrow * SPITCH + lseg,        Ab + _r1 + _lc); \
        CPASYNC16(_sa + STAGE_BYTES + (lrow + 64) * SPITCH + lseg, Ab + _r2 + _lc); \
        CPASYNC16(_sb + lrow * SPITCH + lseg,              Bb + _r1 + _hc);       \
        CPASYNC16(_sb + (lrow + 64) * SPITCH + lseg,       Bb + _r2 + _hc);       \
        CPASYNC16(_sb + STAGE_BYTES + lrow * SPITCH + lseg,        Bb + _r1 + _lc); \
        CPASYNC16(_sb + STAGE_BYTES + (lrow + 64) * SPITCH + lseg, Bb + _r2 + _lc); \
        CP_COMMIT();                                                              \
    } while (0)

    ISSUE_GROUP(0);
    ISSUE_GROUP(1);

    const uint32_t aRowOff = (uint32_t)(wm * 64 + (l & 15)) * SPITCH + (l >> 4) * 16;
    const uint32_t bRowOff = (uint32_t)(wn * 32 + ((l >> 4) * 8 + (l & 7))) * SPITCH +
                             ((l >> 3) & 1) * 16;

    for (int g = 0; g < 8; g++) {
        if (g < 7) CP_WAIT1(); else CP_WAIT0();
        __syncthreads();

        const uint32_t st = (uint32_t)(g & 1) * (2 * STAGE_BYTES);
        const uint32_t aH = sAb + st + aRowOff;
        const uint32_t aL = aH + STAGE_BYTES;
        const uint32_t bH = sBb + st + bRowOff;
        const uint32_t bL = bH + STAGE_BYTES;

#pragma unroll
        for (int ks = 0; ks < 2; ks++) {
            uint32_t ah[4][4], al[4][4], bf[2][4];
#pragma unroll
            for (int mf = 0; mf < 4; mf++)
                LDMX4(ah[mf][0], ah[mf][1], ah[mf][2], ah[mf][3],
                      aH + mf * (16 * SPITCH) + ks * 32);
#pragma unroll
            for (int n2 = 0; n2 < 2; n2++)
                LDMX4(bf[n2][0], bf[n2][1], bf[n2][2], bf[n2][3],
                      bH + n2 * (16 * SPITCH) + ks * 32);
#pragma unroll
            for (int mf = 0; mf < 4; mf++)
#pragma unroll
                for (int nf = 0; nf < 4; nf++)
                    MMA16816(acc[mf][nf], ah[mf],
                             bf[nf >> 1][(nf & 1) * 2],
                             bf[nf >> 1][(nf & 1) * 2 + 1]);
#pragma unroll
            for (int mf = 0; mf < 4; mf++)
                LDMX4(al[mf][0], al[mf][1], al[mf][2], al[mf][3],
                      aL + mf * (16 * SPITCH) + ks * 32);
#pragma unroll
            for (int mf = 0; mf < 4; mf++)
#pragma unroll
                for (int nf = 0; nf < 4; nf++)
                    MMA16816(acc[mf][nf], al[mf],
                             bf[nf >> 1][(nf & 1) * 2],
                             bf[nf >> 1][(nf & 1) * 2 + 1]);
#pragma unroll
            for (int n2 = 0; n2 < 2; n2++)
                LDMX4(bf[n2][0], bf[n2][1], bf[n2][2], bf[n2][3],
                      bL + n2 * (16 * SPITCH) + ks * 32);
#pragma unroll
            for (int mf = 0; mf < 4; mf++)
#pragma unroll
                for (int nf = 0; nf < 4; nf++)
                    MMA16816(acc[mf][nf], ah[mf],
                             bf[nf >> 1][(nf & 1) * 2],
                             bf[nf >> 1][(nf & 1) * 2 + 1]);
        }
        __syncthreads();
        if (g + 2 < 8) ISSUE_GROUP(g + 2);
    }
#undef ISSUE_GROUP

    const int rbase = tileM * 128 + wm * 64 + (l >> 2);
    const int cbase = tileN * 128 + wn * 32 + (l & 3) * 2;
#pragma unroll
    for (int mf = 0; mf < 4; mf++) {
#pragma unroll
        for (int nf = 0; nf < 4; nf++) {
            const int col = cbase + nf * 8;
            const float b0 = bias[col], b1 = bias[col + 1];
            const size_t r0 = (size_t)(rbase + mf * 16) * Ntot + col;
            const size_t r1 = r0 + (size_t)8 * Ntot;
            if (PACK) {
                uint32_t* C = reinterpret_cast<uint32_t*>(Cout);
                *reinterpret_cast<uint2*>(C + r0) =
                    make_uint2(pack_hl(acc[mf][nf][0] + b0), pack_hl(acc[mf][nf][1] + b1));
                *reinterpret_cast<uint2*>(C + r1) =
                    make_uint2(pack_hl(acc[mf][nf][2] + b0), pack_hl(acc[mf][nf][3] + b1));
            } else {
                float* C = reinterpret_cast<float*>(Cout);
                *reinterpret_cast<float2*>(C + r0) =
                    make_float2(acc[mf][nf][0] + b0, acc[mf][nf][1] + b1);
                *reinterpret_cast<float2*>(C + r1) =
                    make_float2(acc[mf][nf][2] + b0, acc[mf][nf][3] + b1);
            }
        }
    }
}

// ======================= tensor-core attention v5 ============================
// warp w owns query rows [w*16, w*16+16) across all 144 keys.
// Q, K, V all staged row-major [144][hi 64B | lo 64B], pitch 144.
// PV B-fragments loaded with ldmatrix.trans directly from row-major V.
// QK loop regrouped: (Qh,Ql) loaded once per ks; Kh serves 2 terms.
#define QPITCH 144
#define KPITCH 144
#define VPITCH 144
#define OFF_Q   0
#define OFF_K   (144 * QPITCH)            /* 20736 */
#define OFF_V   (OFF_K + 144 * KPITCH)    /* 41472 */
#define SMEM_ATTN (OFF_V + 144 * VPITCH)  /* 62208 */

__global__ __launch_bounds__(288, 2) void attn_tc_kernel() {
    extern __shared__ char sm[];
    const uint32_t sb = smem_u32(sm);
    const int tid = threadIdx.x, l = tid & 31, w = tid >> 5;
    const int h = blockIdx.x, b = blockIdx.y;
    const size_t tokBase = (size_t)b * NW;

    // ---- stage Q, K, V (all identical row-major hi|lo format) ----
    for (int idx = tid; idx < 144 * 8; idx += 288) {
        int r = idx >> 3, d4 = (idx & 7) * 4;
        const uint32_t* src = g_qkv + (tokBase + r) * QKVN + h * HD + d4;
        char* dst = sm + r * QPITCH + d4 * 2;   // OFF_Q = 0
#pragma unroll
        for (int mtx = 0; mtx < 3; mtx++) {     // Q, K, V
            uint4 e = *reinterpret_cast<const uint4*>(src + mtx * DIM);
            char* p = dst + mtx * (144 * QPITCH);
            *reinterpret_cast<uint32_t*>(p)      = __byte_perm(e.x, e.y, 0x5410);
            *reinterpret_cast<uint32_t*>(p + 4)  = __byte_perm(e.z, e.w, 0x5410);
            *reinterpret_cast<uint32_t*>(p + 64) = __byte_perm(e.x, e.y, 0x7632);
            *reinterpret_cast<uint32_t*>(p + 68) = __byte_perm(e.z, e.w, 0x7632);
        }
    }
    __syncthreads();    // the only block barrier

    // ---- QK^T: S[16 x 144] per warp; grouped fragment reuse ----
    float accS[18][4];
#pragma unroll
    for (int j = 0; j < 18; j++)
#pragma unroll
        for (int e = 0; e < 4; e++) accS[j][e] = 0.f;

    const uint32_t aBase = sb + OFF_Q + (w * 16 + (l & 15)) * QPITCH + (l >> 4) * 16;
    const uint32_t bBase = sb + OFF_K +
        (((l >> 4) & 1) * 8 + (l & 7)) * KPITCH + ((l >> 3) & 1) * 16;
#pragma unroll
    for (int ks = 0; ks < 2; ks++) {
        uint32_t ah[4], al[4];
        LDMX4(ah[0], ah[1], ah[2], ah[3], aBase + ks * 32);        // Qh
        LDMX4(al[0], al[1], al[2], al[3], aBase + 64 + ks * 32);   // Ql
#pragma unroll
        for (int jp = 0; jp < 9; jp++) {
            uint32_t bf[4];
            LDMX4(bf[0], bf[1], bf[2], bf[3],
                  bBase + jp * (16 * KPITCH) + ks * 32);           // Kh
            MMA16816(accS[jp * 2],     ah, bf[0], bf[1]);
            MMA16816(accS[jp * 2 + 1], ah, bf[2], bf[3]);
            MMA16816(accS[jp * 2],     al, bf[0], bf[1]);
            MMA16816(accS[jp * 2 + 1], al, bf[2], bf[3]);
            LDMX4(bf[0], bf[1], bf[2], bf[3],
                  bBase + jp * (16 * KPITCH) + 64 + ks * 32);      // Kl
            MMA16816(accS[jp * 2],     ah, bf[0], bf[1]);
            MMA16816(accS[jp * 2 + 1], ah, bf[2], bf[3]);
        }
    }

    // ---- bias add + row max (register + quad shuffle only) ----
    const float* bh = g_bias + h * (NW * NW);
    const int r0 = w * 16 + (l >> 2);
    float rmax0 = -1e30f, rmax1 = -1e30f;
#pragma unroll
    for (int j = 0; j < 18; j++) {
        const int c = j * 8 + (l & 3) * 2;
        float2 b0 = *reinterpret_cast<const float2*>(bh + r0 * NW + c);
        float2 b1 = *reinterpret_cast<const float2*>(bh + (r0 + 8) * NW + c);
        accS[j][0] += b0.x; accS[j][1] += b0.y;
        accS[j][2] += b1.x; accS[j][3] += b1.y;
        rmax0 = fmaxf(rmax0, fmaxf(accS[j][0], accS[j][1]));
        rmax1 = fmaxf(rmax1, fmaxf(accS[j][2], accS[j][3]));
    }
#pragma unroll
    for (int o = 1; o <= 2; o <<= 1) {
        rmax0 = fmaxf(rmax0, __shfl_xor_sync(0xffffffff, rmax0, o));
        rmax1 = fmaxf(rmax1, __shfl_xor_sync(0xffffffff, rmax1, o));
    }

    // ---- exp + row sum ----
    float rsum0 = 0.f, rsum1 = 0.f;
#pragma unroll
    for (int j = 0; j < 18; j++) {
        accS[j][0] = __expf(accS[j][0] - rmax0);
        accS[j][1] = __expf(accS[j][1] - rmax0);
        accS[j][2] = __expf(accS[j][2] - rmax1);
        accS[j][3] = __expf(accS[j][3] - rmax1);
        rsum0 += accS[j][0] + accS[j][1];
        rsum1 += accS[j][2] + accS[j][3];
    }
#pragma unroll
    for (int o = 1; o <= 2; o <<= 1) {
        rsum0 += __shfl_xor_sync(0xffffffff, rsum0, o);
        rsum1 += __shfl_xor_sync(0xffffffff, rsum1, o);
    }
    const float inv0 = 1.0f / rsum0;
    const float inv1 = 1.0f / rsum1;

    // ---- PV: inline P conversion; V via ldmatrix.trans from row-major ----
    float accO[4][4];
#pragma unroll
    for (int j = 0; j < 4; j++)
#pragma unroll
        for (int e = 0; e < 4; e++) accO[j][e] = 0.f;

    // lane address: row = key m = (l&15), col 16B-half = (l>>4) selects d 8..16
    const uint32_t vLane = sb + OFF_V + (l & 15) * VPITCH + (l >> 4) * 16;
#pragma unroll
    for (int kk = 0; kk < 9; kk++) {
        uint32_t ph[4], pl[4];
        {
            const int j0 = 2 * kk, j1 = 2 * kk + 1;
            split2(accS[j0][0] * inv0, accS[j0][1] * inv0, ph[0], pl[0]);
            split2(accS[j0][2] * inv1, accS[j0][3] * inv1, ph[1], pl[1]);
            split2(accS[j1][0] * inv0, accS[j1][1] * inv0, ph[2], pl[2]);
            split2(accS[j1][2] * inv1, accS[j1][3] * inv1, ph[3], pl[3]);
        }
        const uint32_t vk = vLane + kk * (16 * VPITCH);
        // jpair 0: d tiles 0,1 (cols 0..16B)  |  jpair 1: d tiles 2,3 (+32B)
#pragma unroll
        for (int jp = 0; jp < 2; jp++) {
            uint32_t vf[4];
            LDMX4T(vf[0], vf[1], vf[2], vf[3], vk + jp * 32);        // Vh
            MMA16816(accO[2 * jp],     ph, vf[0], vf[1]);
            MMA16816(accO[2 * jp + 1], ph, vf[2], vf[3]);
            MMA16816(accO[2 * jp],     pl, vf[0], vf[1]);
            MMA16816(accO[2 * jp + 1], pl, vf[2], vf[3]);
            LDMX4T(vf[0], vf[1], vf[2], vf[3], vk + jp * 32 + 64);   // Vl
            MMA16816(accO[2 * jp],     ph, vf[0], vf[1]);
            MMA16816(accO[2 * jp + 1], ph, vf[2], vf[3]);
        }
    }

    // ---- write O ext [Oh|Ol] directly ----
#pragma unroll
    for (int j = 0; j < 4; j++) {
        const int cc = j * 8 + (l & 3) * 2;
        uint32_t hp0, lp0, hp1, lp1;
        split2(accO[j][0], accO[j][1], hp0, lp0);
        split2(accO[j][2], accO[j][3], hp1, lp1);
        __nv_bfloat16* o0 = g_attx + (tokBase + r0) * KSTORE + h * HD + cc;
        __nv_bfloat16* o1 = g_attx + (tokBase + r0 + 8) * KSTORE + h * HD + cc;
        *reinterpret_cast<uint32_t*>(o0)       = hp0;
        *reinterpret_cast<uint32_t*>(o0 + 256) = lp0;
        *reinterpret_cast<uint32_t*>(o1)       = hp1;
        *reinterpret_cast<uint32_t*>(o1 + 256) = lp1;
    }
}

// ---------------- launch ------------------------------------------------------
extern "C" void kernel_launch(void* const* d_in, const int* in_sizes, int n_in,
                              void* d_out, int out_size) {
    const float* x      = (const float*)d_in[0];
    const float* qkv_w  = (const float*)d_in[1];
    const float* qkv_b  = (const float*)d_in[2];
    const float* proj_w = (const float*)d_in[3];
    const float* proj_b = (const float*)d_in[4];
    const float* rpb    = (const float*)d_in[5];
    const int*   rel    = (const int*)d_in[6];

    uint32_t* qkvbuf = nullptr;
    __nv_bfloat16 *axp = nullptr, *attxp = nullptr, *bqp = nullptr, *bpp = nullptr;
    float* sbp = nullptr;
    cudaGetSymbolAddress((void**)&qkvbuf, g_qkv);
    cudaGetSymbolAddress((void**)&axp,   g_ax);
    cudaGetSymbolAddress((void**)&attxp, g_attx);
    cudaGetSymbolAddress((void**)&bqp,   g_bq);
    cudaGetSymbolAddress((void**)&bpp,   g_bp);
    cudaGetSymbolAddress((void**)&sbp,   g_sbias);

    static bool attr_done = false;
    if (!attr_done) {
        cudaFuncSetAttribute(attn_tc_kernel,
                             cudaFuncAttributeMaxDynamicSharedMemorySize, SMEM_ATTN);
        cudaFuncSetAttribute(gemm_mma_kernel<true>,
                             cudaFuncAttributeMaxDynamicSharedMemorySize, SMEM_GEMM);
        cudaFuncSetAttribute(gemm_mma_kernel<false>,
                             cudaFuncAttributeMaxDynamicSharedMemorySize, SMEM_GEMM);
        attr_done = true;
    }

    // order: profiled launch slot (index 3) = attention
    conv_x_kernel<<<(NTOK * 64) / 256, 256>>>(x);                    // 0
    prep_wb_kernel<<<1108, 256>>>(qkv_w, proj_w, rpb, rel, qkv_b);   // 1
    gemm_mma_kernel<true><<<dim3(QKVN / 128, NTOK / 128), 256, SMEM_GEMM>>>(
        axp, bqp, sbp, qkvbuf, QKVN);                                // 2
    attn_tc_kernel<<<dim3(NH, BnW), 288, SMEM_ATTN>>>();             // 3 <- profiled
    gemm_mma_kernel<false><<<dim3(DIM / 128, NTOK / 128), 256, SMEM_GEMM>>>(
        attxp, bpp, proj_b, d_out, DIM);                             // 4
}